// round 1
// baseline (speedup 1.0000x reference)
#include <cuda_runtime.h>
#include <math.h>

#define BB 8
#define CH 128
#define CC 256
#define HH 64
#define WW 64
#define HW 4096
#define PP 32768      // BB*HW
#define KBIG 1152     // 128 ic * 9 taps

// ---------------- scratch (static device globals; no runtime alloc) --------
static __device__ float  g_x  [BB*CC*HW];     // concat(x2, up(x1))
static __device__ float  g_h1 [BB*CC*HW];     // depthwise1 out
static __device__ float  g_h  [BB*CH*HW];     // pointwise out
static __device__ float  g_offb[BB*18*HW];    // offsets
static __device__ float  g_mb [BB*9*HW];      // modulation (sigmoid)
static __device__ int4   g_si [9*PP];         // corner indices (-1 => zero pad)
static __device__ float4 g_sw [9*PP];         // bilinear weights * modulation
static __device__ float  g_v  [(size_t)KBIG*PP]; // sampled matrix [k][pxg]
static __device__ float  g_d  [BB*CH*HW];     // deform conv out
static __device__ float  g_t  [BB*CH*HW];     // gelu(bn1) out
static __device__ float  g_u  [BB*CH*HW];     // depthwise2 out
static __device__ float  g_s1 [2*CH];         // bn1 mean / rstd
static __device__ float  g_s2 [2*CH];         // bn2 mean / rstd

// ---------------- K1: bilinear up2x (align_corners) + concat ---------------
__global__ __launch_bounds__(256) void k_upcat(const float* __restrict__ x1,
                                               const float* __restrict__ x2) {
    int i = blockIdx.x * 256 + threadIdx.x;
    if (i >= BB*CC*HW) return;
    int hw = i & (HW-1);
    int ch = (i >> 12) & (CC-1);
    int b  = i >> 20;
    float v;
    if (ch < CH) {
        v = x2[(b*CH + ch)*HW + hw];
    } else {
        int c1 = ch - CH;
        int r = hw >> 6, c = hw & 63;
        float sr = (float)r * (31.0f/63.0f);
        float sc = (float)c * (31.0f/63.0f);
        int i0 = min((int)floorf(sr), 30);
        int j0 = min((int)floorf(sc), 30);
        float ty = sr - (float)i0;
        float tx = sc - (float)j0;
        const float* img = x1 + ((size_t)(b*CH + c1))*1024;
        float a00 = img[i0*32 + j0],     a10 = img[(i0+1)*32 + j0];
        float a01 = img[i0*32 + j0 + 1], a11 = img[(i0+1)*32 + j0 + 1];
        v = (a00*(1.f-ty) + a10*ty)*(1.f-tx) + (a01*(1.f-ty) + a11*ty)*tx;
    }
    g_x[i] = v;
}

// ---------------- K2: depthwise 3x3 (256 ch) + bias ------------------------
__global__ __launch_bounds__(256) void k_dw1(const float* __restrict__ w,
                                             const float* __restrict__ bias) {
    int i = blockIdx.x * 256 + threadIdx.x;
    if (i >= BB*CC*HW) return;
    int hw = i & (HW-1);
    int ch = (i >> 12) & (CC-1);
    int b  = i >> 20;
    int r = hw >> 6, c = hw & 63;
    const float* img = g_x + (size_t)(b*CC + ch)*HW;
    const float* wc  = w + ch*9;
    float acc = bias[ch];
#pragma unroll
    for (int dy = -1; dy <= 1; dy++)
#pragma unroll
        for (int dx = -1; dx <= 1; dx++) {
            int rr = r + dy, cc = c + dx;
            if ((unsigned)rr < 64u && (unsigned)cc < 64u)
                acc += wc[(dy+1)*3 + (dx+1)] * img[rr*64 + cc];
        }
    g_h1[i] = acc;
}

// ---------------- K3: pointwise 256->128 GEMM (tiled) ----------------------
// grid: PP/32 tiles; block 256 thr; thread tile 4oc x 4px; K-chunks of 32
__global__ __launch_bounds__(256) void k_pw(const float* __restrict__ w,
                                            const float* __restrict__ bias) {
    __shared__ float Ws[32*132];  // [kk][oc], padded
    __shared__ float Bs[32*36];   // [kk][px], padded
    int tile = blockIdx.x;
    int b   = tile >> 7;           // 128 tiles per batch
    int hw0 = (tile & 127) * 32;
    int tid = threadIdx.x;
    int oc0 = (tid >> 3) << 2;     // 0..124
    int px0 = (tid & 7) << 2;      // 0..28
    float acc[4][4];
#pragma unroll
    for (int ii = 0; ii < 4; ii++)
#pragma unroll
        for (int jj = 0; jj < 4; jj++) acc[ii][jj] = 0.f;

    for (int kc = 0; kc < 8; kc++) {
        int ic0 = kc * 32;
#pragma unroll
        for (int e = tid; e < 4096; e += 256) {
            int oc = e >> 5, kk = e & 31;
            Ws[kk*132 + oc] = w[oc*256 + ic0 + kk];
        }
#pragma unroll
        for (int e = tid; e < 1024; e += 256) {
            int kk = e >> 5, j = e & 31;
            Bs[kk*36 + j] = g_h1[(size_t)(b*CC + ic0 + kk)*HW + hw0 + j];
        }
        __syncthreads();
#pragma unroll
        for (int kk = 0; kk < 32; kk++) {
            float4 wv = *(const float4*)&Ws[kk*132 + oc0];
            float4 bv = *(const float4*)&Bs[kk*36 + px0];
            float wr[4] = {wv.x, wv.y, wv.z, wv.w};
            float br[4] = {bv.x, bv.y, bv.z, bv.w};
#pragma unroll
            for (int ii = 0; ii < 4; ii++)
#pragma unroll
                for (int jj = 0; jj < 4; jj++) acc[ii][jj] += wr[ii]*br[jj];
        }
        __syncthreads();
    }
#pragma unroll
    for (int ii = 0; ii < 4; ii++) {
        float bb = bias[oc0 + ii];
#pragma unroll
        for (int jj = 0; jj < 4; jj++)
            g_h[(size_t)(b*CH + oc0 + ii)*HW + hw0 + px0 + jj] = acc[ii][jj] + bb;
    }
}

// ---------------- K4: offset(18) + mask(9) 3x3 conv, fused -----------------
// grid: 128 blocks (256 px each); weights [k][27] in dynamic smem
__global__ __launch_bounds__(256) void k_offmask(const float* __restrict__ pw,
                                                 const float* __restrict__ pb,
                                                 const float* __restrict__ mw,
                                                 const float* __restrict__ mb) {
    extern __shared__ float Ws[];  // 1152*27 floats
    int tid = threadIdx.x;
    int blk = blockIdx.x;
    int b   = blk >> 4;
    int hw0 = (blk & 15) * 256;

    for (int e = tid; e < KBIG*27; e += 256) {
        int k = e / 27, oc = e - k*27;
        Ws[e] = (oc < 18) ? pw[oc*KBIG + k] : mw[(oc-18)*KBIG + k];
    }
    __syncthreads();

    int pix = hw0 + tid;
    int r = pix >> 6, c = pix & 63;
    int noff[9];
#pragma unroll
    for (int t = 0; t < 9; t++) {
        int dy = t/3 - 1, dx = t%3 - 1;
        int rr = r + dy, cc = c + dx;
        noff[t] = ((unsigned)rr < 64u && (unsigned)cc < 64u) ? (rr*64 + cc) : -1;
    }
    float acc[27];
#pragma unroll
    for (int oc = 0; oc < 18; oc++) acc[oc] = pb[oc];
#pragma unroll
    for (int oc = 0; oc < 9;  oc++) acc[18+oc] = mb[oc];

    for (int ic = 0; ic < CH; ic++) {
        const float* img = g_h + (size_t)(b*CH + ic)*HW;
#pragma unroll
        for (int t = 0; t < 9; t++) {
            float v = (noff[t] >= 0) ? img[noff[t]] : 0.f;
            const float* wr = Ws + (ic*9 + t)*27;
#pragma unroll
            for (int oc = 0; oc < 27; oc++) acc[oc] += v * wr[oc];
        }
    }
#pragma unroll
    for (int oc = 0; oc < 18; oc++)
        g_offb[(size_t)(b*18 + oc)*HW + pix] = acc[oc];
#pragma unroll
    for (int j = 0; j < 9; j++)
        g_mb[(size_t)(b*9 + j)*HW + pix] = 1.f / (1.f + expf(-acc[18+j]));
}

// ---------------- K5a: sampling metadata per (n, pixel) --------------------
__global__ __launch_bounds__(256) void k_meta() {
    int i = blockIdx.x * 256 + threadIdx.x;
    if (i >= 9*PP) return;
    int n   = i / PP;
    int pxg = i - n*PP;
    int b   = pxg >> 12;
    int hw  = pxg & 4095;
    int r = hw >> 6, c = hw & 63;
    float ox = g_offb[(size_t)(b*18 + n)*HW + hw];
    float oy = g_offb[(size_t)(b*18 + 9 + n)*HW + hw];
    float px = (float)(r + 1) + (float)(n/3 - 1) + ox;
    float py = (float)(c + 1) + (float)(n%3 - 1) + oy;
    float fx = floorf(px), fy = floorf(py);
    float qx0 = fminf(fmaxf(fx,       0.f), 65.f);
    float qx1 = fminf(fmaxf(fx + 1.f, 0.f), 65.f);
    float qy0 = fminf(fmaxf(fy,       0.f), 65.f);
    float qy1 = fminf(fmaxf(fy + 1.f, 0.f), 65.f);
    float pxc = fminf(fmaxf(px, 0.f), 65.f);
    float pyc = fminf(fmaxf(py, 0.f), 65.f);
    float glt = (1.f + (qx0 - pxc)) * (1.f + (qy0 - pyc));
    float grb = (1.f - (qx1 - pxc)) * (1.f - (qy1 - pyc));
    float glb = (1.f + (qx0 - pxc)) * (1.f - (qy1 - pyc));
    float grt = (1.f - (qx1 - pxc)) * (1.f + (qy0 - pyc));
    float mod = g_mb[(size_t)(b*9 + n)*HW + hw];
    int ix0 = (int)qx0, ix1 = (int)qx1, iy0 = (int)qy0, iy1 = (int)qy1;
#define ENC(qx,qy) (((qx)>=1 && (qx)<=64 && (qy)>=1 && (qy)<=64) ? (((qx)-1)*64 + ((qy)-1)) : -1)
    g_si[i] = make_int4(ENC(ix0,iy0), ENC(ix1,iy1), ENC(ix0,iy1), ENC(ix1,iy0));
#undef ENC
    g_sw[i] = make_float4(glt*mod, grb*mod, glb*mod, grt*mod);
}

// ---------------- K5b: gather/interp -> g_v[k][pxg] ------------------------
// grid: 256 blocks = (b, hw-chunk of 128); meta staged in smem, loop ic
__global__ __launch_bounds__(256) void k_sample() {
    __shared__ int4   si[9*128];
    __shared__ float4 sw[9*128];
    int tid = threadIdx.x;
    int b   = blockIdx.x >> 5;
    int hw0 = (blockIdx.x & 31) * 128;
#pragma unroll
    for (int e = tid; e < 1152; e += 256) {
        int n = e >> 7, h = e & 127;
        si[e] = g_si[(size_t)n*PP + b*HW + hw0 + h];
        sw[e] = g_sw[(size_t)n*PP + b*HW + hw0 + h];
    }
    __syncthreads();
    for (int ic = 0; ic < CH; ic++) {
        const float* img = g_h + (size_t)(b*CH + ic)*HW;
#pragma unroll
        for (int e = tid; e < 1152; e += 256) {
            int4   id = si[e];
            float4 w  = sw[e];
            float v = 0.f;
            if (id.x >= 0) v += w.x * img[id.x];
            if (id.y >= 0) v += w.y * img[id.y];
            if (id.z >= 0) v += w.z * img[id.z];
            if (id.w >= 0) v += w.w * img[id.w];
            int n = e >> 7, h = e & 127;
            g_v[(size_t)(ic*9 + n)*PP + b*HW + hw0 + h] = v;
        }
    }
}

// ---------------- K5c: deform GEMM 128 x 1152 x 32768 ----------------------
// grid: 512 blocks of 64 px; 256 thr; thread tile 4oc x 8px; K-chunks of 16
__global__ __launch_bounds__(256) void k_dgemm(const float* __restrict__ w) {
    __shared__ float Ws[16*132];  // [kk][oc] padded
    __shared__ float Vs[16*64];   // [kk][px]
    int tid  = threadIdx.x;
    int pxg0 = blockIdx.x * 64;
    int b    = pxg0 >> 12;
    int hw0  = pxg0 & 4095;
    int oc0  = (tid >> 3) << 2;   // 0..124
    int px0  = (tid & 7) << 3;    // 0..56
    float acc[4][8];
#pragma unroll
    for (int ii = 0; ii < 4; ii++)
#pragma unroll
        for (int jj = 0; jj < 8; jj++) acc[ii][jj] = 0.f;

    for (int kc = 0; kc < KBIG/16; kc++) {
        int k0 = kc * 16;
#pragma unroll
        for (int e = tid; e < 2048; e += 256) {
            int oc = e >> 4, kk = e & 15;
            Ws[kk*132 + oc] = w[oc*KBIG + k0 + kk];
        }
#pragma unroll
        for (int e = tid; e < 1024; e += 256) {
            int kk = e >> 6, j = e & 63;
            Vs[kk*64 + j] = g_v[(size_t)(k0 + kk)*PP + pxg0 + j];
        }
        __syncthreads();
#pragma unroll
        for (int kk = 0; kk < 16; kk++) {
            float4 wv  = *(const float4*)&Ws[kk*132 + oc0];
            float4 bv0 = *(const float4*)&Vs[kk*64 + px0];
            float4 bv1 = *(const float4*)&Vs[kk*64 + px0 + 4];
            float wr[4] = {wv.x, wv.y, wv.z, wv.w};
            float br[8] = {bv0.x, bv0.y, bv0.z, bv0.w, bv1.x, bv1.y, bv1.z, bv1.w};
#pragma unroll
            for (int ii = 0; ii < 4; ii++)
#pragma unroll
                for (int jj = 0; jj < 8; jj++) acc[ii][jj] += wr[ii]*br[jj];
        }
        __syncthreads();
    }
#pragma unroll
    for (int ii = 0; ii < 4; ii++)
#pragma unroll
        for (int jj = 0; jj < 8; jj++)
            g_d[(size_t)(b*CH + oc0 + ii)*HW + hw0 + px0 + jj] = acc[ii][jj];
}

// ---------------- stats: per-channel mean / rstd over (B,H,W) --------------
__global__ __launch_bounds__(256) void k_stats(const float* __restrict__ src,
                                               float* __restrict__ dst) {
    __shared__ float ss[256], sq[256];
    int ch = blockIdx.x, tid = threadIdx.x;
    float s = 0.f, s2 = 0.f;
    for (int i = tid; i < BB*HW; i += 256) {
        int b = i >> 12, hw = i & 4095;
        float v = src[(size_t)(b*CH + ch)*HW + hw];
        s += v; s2 += v*v;
    }
    ss[tid] = s; sq[tid] = s2;
    __syncthreads();
    for (int o = 128; o > 0; o >>= 1) {
        if (tid < o) { ss[tid] += ss[tid+o]; sq[tid] += sq[tid+o]; }
        __syncthreads();
    }
    if (tid == 0) {
        float mean = ss[0] * (1.f/32768.f);
        float var  = sq[0] * (1.f/32768.f) - mean*mean;
        dst[ch]      = mean;
        dst[CH + ch] = rsqrtf(var + 1e-5f);
    }
}

// ---------------- K7a: bn1 + exact gelu ------------------------------------
__global__ __launch_bounds__(256) void k_bn1gelu(const float* __restrict__ g,
                                                 const float* __restrict__ bv) {
    int i = blockIdx.x * 256 + threadIdx.x;
    if (i >= BB*CH*HW) return;
    int ch = (i >> 12) & (CH-1);
    float xn = (g_d[i] - g_s1[ch]) * g_s1[CH+ch] * g[ch] + bv[ch];
    g_t[i] = 0.5f * xn * (1.f + erff(xn * 0.70710678118654752f));
}

// ---------------- K7b: depthwise2 3x3 + bias --------------------------------
__global__ __launch_bounds__(256) void k_dw2(const float* __restrict__ w,
                                             const float* __restrict__ bias) {
    int i = blockIdx.x * 256 + threadIdx.x;
    if (i >= BB*CH*HW) return;
    int hw = i & (HW-1);
    int ch = (i >> 12) & (CH-1);
    int b  = i >> 19;
    int r = hw >> 6, c = hw & 63;
    const float* img = g_t + (size_t)(b*CH + ch)*HW;
    const float* wc  = w + ch*9;
    float acc = bias[ch];
#pragma unroll
    for (int dy = -1; dy <= 1; dy++)
#pragma unroll
        for (int dx = -1; dx <= 1; dx++) {
            int rr = r + dy, cc = c + dx;
            if ((unsigned)rr < 64u && (unsigned)cc < 64u)
                acc += wc[(dy+1)*3 + (dx+1)] * img[rr*64 + cc];
        }
    g_u[i] = acc;
}

// ---------------- K9: bn2 + relu -> out -------------------------------------
__global__ __launch_bounds__(256) void k_bn2relu(const float* __restrict__ g,
                                                 const float* __restrict__ bv,
                                                 float* __restrict__ out) {
    int i = blockIdx.x * 256 + threadIdx.x;
    if (i >= BB*CH*HW) return;
    int ch = (i >> 12) & (CH-1);
    float xn = (g_u[i] - g_s2[ch]) * g_s2[CH+ch] * g[ch] + bv[ch];
    out[i] = fmaxf(xn, 0.f);
}

// ---------------- launch ----------------------------------------------------
extern "C" void kernel_launch(void* const* d_in, const int* in_sizes, int n_in,
                              void* d_out, int out_size) {
    const float* x1      = (const float*)d_in[0];
    const float* x2      = (const float*)d_in[1];
    const float* dw1_w   = (const float*)d_in[2];
    const float* dw1_b   = (const float*)d_in[3];
    const float* pw_w    = (const float*)d_in[4];
    const float* pw_b    = (const float*)d_in[5];
    const float* p_w     = (const float*)d_in[6];
    const float* p_b     = (const float*)d_in[7];
    const float* m_w     = (const float*)d_in[8];
    const float* m_b     = (const float*)d_in[9];
    const float* dcn_w   = (const float*)d_in[10];
    const float* bn1_g   = (const float*)d_in[11];
    const float* bn1_b   = (const float*)d_in[12];
    const float* dw2_w   = (const float*)d_in[13];
    const float* dw2_b   = (const float*)d_in[14];
    const float* bn2_g   = (const float*)d_in[15];
    const float* bn2_b   = (const float*)d_in[16];
    float* out = (float*)d_out;

    // stats buffer device pointers
    float *s1p, *s2p;
    cudaGetSymbolAddress((void**)&s1p, g_s1);
    cudaGetSymbolAddress((void**)&s2p, g_s2);
    float *dp, *up;
    cudaGetSymbolAddress((void**)&dp, g_d);
    cudaGetSymbolAddress((void**)&up, g_u);

    const int smemK4 = KBIG * 27 * (int)sizeof(float); // 124416 B
    cudaFuncSetAttribute(k_offmask, cudaFuncAttributeMaxDynamicSharedMemorySize, smemK4);

    k_upcat<<<(BB*CC*HW + 255)/256, 256>>>(x1, x2);
    k_dw1  <<<(BB*CC*HW + 255)/256, 256>>>(dw1_w, dw1_b);
    k_pw   <<<PP/32, 256>>>(pw_w, pw_b);
    k_offmask<<<128, 256, smemK4>>>(p_w, p_b, m_w, m_b);
    k_meta <<<(9*PP + 255)/256, 256>>>();
    k_sample<<<256, 256>>>();
    k_dgemm<<<PP/64, 256>>>(dcn_w);
    k_stats<<<CH, 256>>>(dp, s1p);
    k_bn1gelu<<<(BB*CH*HW + 255)/256, 256>>>(bn1_g, bn1_b);
    k_dw2  <<<(BB*CH*HW + 255)/256, 256>>>(dw2_w, dw2_b);
    k_stats<<<CH, 256>>>(up, s2p);
    k_bn2relu<<<(BB*CH*HW + 255)/256, 256>>>(bn2_g, bn2_b, out);
}

// round 2
// speedup vs baseline: 1.0525x; 1.0525x over previous
#include <cuda_runtime.h>
#include <math.h>

#define BB 8
#define CH 128
#define CC 256
#define HW 4096
#define PP 32768      // BB*HW
#define KBIG 1152     // 128 ic * 9 taps

// ---------------- scratch (static device globals; no runtime alloc) --------
static __device__ float  g_x  [BB*CC*HW];     // concat(x2, up(x1))
static __device__ float  g_h1 [BB*CC*HW];     // depthwise1 out
static __device__ float  g_h  [BB*CH*HW];     // pointwise out
static __device__ float  g_offb[BB*18*HW];    // offsets
static __device__ float  g_mb [BB*9*HW];      // modulation (sigmoid)
static __device__ float  g_d  [BB*CH*HW];     // deform conv out
static __device__ float  g_t  [BB*CH*HW];     // gelu(bn1) out
static __device__ float  g_u  [BB*CH*HW];     // depthwise2 out
static __device__ float  g_s1 [2*CH];         // bn1 mean / rstd
static __device__ float  g_s2 [2*CH];         // bn2 mean / rstd
static __device__ float  g_wT  [KBIG*CH];     // dcn_w transposed [k][oc]
static __device__ float  g_pwT [CC*CH];       // pw_w transposed  [k][oc]
static __device__ float  g_omwT[KBIG*32];     // offset+mask w    [k][oc32]

// ---------------- K0: weight transposes -------------------------------------
__global__ __launch_bounds__(256) void k_prep(const float* __restrict__ dcn_w,
                                              const float* __restrict__ pw_w,
                                              const float* __restrict__ p_w,
                                              const float* __restrict__ m_w) {
    int i = blockIdx.x * 256 + threadIdx.x;
    if (i < KBIG*CH) {
        int k = i >> 7, oc = i & 127;
        g_wT[i] = dcn_w[oc*KBIG + k];
        return;
    }
    i -= KBIG*CH;
    if (i < CC*CH) {
        int k = i >> 7, oc = i & 127;
        g_pwT[i] = pw_w[oc*CC + k];
        return;
    }
    i -= CC*CH;
    if (i < KBIG*32) {
        int k = i >> 5, oc = i & 31;
        float v = 0.f;
        if (oc < 18)      v = p_w[oc*KBIG + k];
        else if (oc < 27) v = m_w[(oc-18)*KBIG + k];
        g_omwT[i] = v;
    }
}

// ---------------- K1: bilinear up2x (align_corners) + concat ---------------
__global__ __launch_bounds__(256) void k_upcat(const float* __restrict__ x1,
                                               const float* __restrict__ x2) {
    int i = blockIdx.x * 256 + threadIdx.x;
    if (i >= BB*CC*HW) return;
    int hw = i & (HW-1);
    int ch = (i >> 12) & (CC-1);
    int b  = i >> 20;
    float v;
    if (ch < CH) {
        v = x2[(b*CH + ch)*HW + hw];
    } else {
        int c1 = ch - CH;
        int r = hw >> 6, c = hw & 63;
        float sr = (float)r * (31.0f/63.0f);
        float sc = (float)c * (31.0f/63.0f);
        int i0 = min((int)floorf(sr), 30);
        int j0 = min((int)floorf(sc), 30);
        float ty = sr - (float)i0;
        float tx = sc - (float)j0;
        const float* img = x1 + ((size_t)(b*CH + c1))*1024;
        float a00 = img[i0*32 + j0],     a10 = img[(i0+1)*32 + j0];
        float a01 = img[i0*32 + j0 + 1], a11 = img[(i0+1)*32 + j0 + 1];
        v = (a00*(1.f-ty) + a10*ty)*(1.f-tx) + (a01*(1.f-ty) + a11*ty)*tx;
    }
    g_x[i] = v;
}

// ---------------- K2: depthwise 3x3 (256 ch) + bias ------------------------
__global__ __launch_bounds__(256) void k_dw1(const float* __restrict__ w,
                                             const float* __restrict__ bias) {
    int i = blockIdx.x * 256 + threadIdx.x;
    if (i >= BB*CC*HW) return;
    int hw = i & (HW-1);
    int ch = (i >> 12) & (CC-1);
    int b  = i >> 20;
    int r = hw >> 6, c = hw & 63;
    const float* img = g_x + (size_t)(b*CC + ch)*HW;
    const float* wc  = w + ch*9;
    float acc = bias[ch];
#pragma unroll
    for (int dy = -1; dy <= 1; dy++)
#pragma unroll
        for (int dx = -1; dx <= 1; dx++) {
            int rr = r + dy, cc = c + dx;
            if ((unsigned)rr < 64u && (unsigned)cc < 64u)
                acc += wc[(dy+1)*3 + (dx+1)] * img[rr*64 + cc];
        }
    g_h1[i] = acc;
}

// ---------------- K3: pointwise 256->128 GEMM, 128oc x 128px tiles ----------
// 256 thr, thread tile 8oc x 8px, K-chunks of 16
__global__ __launch_bounds__(256) void k_pw(const float* __restrict__ bias) {
    __shared__ float Ws[16*132];
    __shared__ float Vs[16*128];
    int tid  = threadIdx.x;
    int pxg0 = blockIdx.x * 128;
    int b    = pxg0 >> 12;
    int hw0  = pxg0 & 4095;
    int oc0  = (tid >> 4) * 8;
    int px0  = (tid & 15) * 8;
    float acc[8][8];
#pragma unroll
    for (int ii = 0; ii < 8; ii++)
#pragma unroll
        for (int jj = 0; jj < 8; jj++) acc[ii][jj] = 0.f;

    for (int kc = 0; kc < 16; kc++) {
        int k0 = kc * 16;
#pragma unroll
        for (int e = tid; e < 2048; e += 256) {
            int kk = e >> 7, oc = e & 127;
            Ws[kk*132 + oc] = g_pwT[(k0 + kk)*CH + oc];
        }
#pragma unroll
        for (int e = tid; e < 2048; e += 256) {
            int kk = e >> 7, j = e & 127;
            Vs[kk*128 + j] = g_h1[(size_t)(b*CC + k0 + kk)*HW + hw0 + j];
        }
        __syncthreads();
#pragma unroll
        for (int kk = 0; kk < 16; kk++) {
            float4 a0 = *(const float4*)&Ws[kk*132 + oc0];
            float4 a1 = *(const float4*)&Ws[kk*132 + oc0 + 4];
            float4 b0 = *(const float4*)&Vs[kk*128 + px0];
            float4 b1 = *(const float4*)&Vs[kk*128 + px0 + 4];
            float ar[8] = {a0.x,a0.y,a0.z,a0.w,a1.x,a1.y,a1.z,a1.w};
            float br[8] = {b0.x,b0.y,b0.z,b0.w,b1.x,b1.y,b1.z,b1.w};
#pragma unroll
            for (int ii = 0; ii < 8; ii++)
#pragma unroll
                for (int jj = 0; jj < 8; jj++) acc[ii][jj] += ar[ii]*br[jj];
        }
        __syncthreads();
    }
#pragma unroll
    for (int ii = 0; ii < 8; ii++) {
        float bb = bias[oc0 + ii];
#pragma unroll
        for (int jj = 0; jj < 8; jj++)
            g_h[(size_t)(b*CH + oc0 + ii)*HW + hw0 + px0 + jj] = acc[ii][jj] + bb;
    }
}

// ---------------- K4: offset(18)+mask(9) conv as GEMM, 32oc x 128px ---------
// 128 thr, thread tile 4oc x 8px, K-chunk = 2 ic (18 k)
__global__ __launch_bounds__(128) void k_offmask(const float* __restrict__ pb,
                                                 const float* __restrict__ mb) {
    __shared__ float Ws[18*36];
    __shared__ float Vs[18*128];
    __shared__ int   noff[9*128];
    int tid  = threadIdx.x;
    int pxg0 = blockIdx.x * 128;
    int b    = pxg0 >> 12;
    int hw0  = pxg0 & 4095;
    int oc0  = (tid >> 4) * 4;   // 8 groups x 4 oc = 32
    int px0  = (tid & 15) * 8;   // 16 groups x 8 px = 128

    // border-masked neighbor offsets per (tap, px)
    for (int e = tid; e < 1152; e += 128) {
        int t = e >> 7, h = e & 127;
        int hw = hw0 + h;
        int r = hw >> 6, c = hw & 63;
        int dy = t/3 - 1, dx = t%3 - 1;
        int rr = r + dy, cc = c + dx;
        noff[e] = ((unsigned)rr < 64u && (unsigned)cc < 64u) ? (rr*64 + cc) : -1;
    }
    __syncthreads();

    float acc[4][8];
#pragma unroll
    for (int ii = 0; ii < 4; ii++)
#pragma unroll
        for (int jj = 0; jj < 8; jj++) acc[ii][jj] = 0.f;

    for (int ic0 = 0; ic0 < CH; ic0 += 2) {
        for (int e = tid; e < 576; e += 128) {
            int kk = e >> 5, oc = e & 31;
            Ws[kk*36 + oc] = g_omwT[(ic0*9 + kk)*32 + oc];
        }
        for (int e = tid; e < 2304; e += 128) {
            int kk = e >> 7, h = e & 127;
            int ic = ic0 + (kk >= 9 ? 1 : 0);
            int t  = kk >= 9 ? kk - 9 : kk;
            int idx = noff[t*128 + h];
            const float* img = g_h + (size_t)(b*CH + ic)*HW;
            Vs[kk*128 + h] = (idx >= 0) ? img[idx] : 0.f;
        }
        __syncthreads();
#pragma unroll
        for (int kk = 0; kk < 18; kk++) {
            float4 a0 = *(const float4*)&Ws[kk*36 + oc0];
            float4 b0 = *(const float4*)&Vs[kk*128 + px0];
            float4 b1 = *(const float4*)&Vs[kk*128 + px0 + 4];
            float ar[4] = {a0.x,a0.y,a0.z,a0.w};
            float br[8] = {b0.x,b0.y,b0.z,b0.w,b1.x,b1.y,b1.z,b1.w};
#pragma unroll
            for (int ii = 0; ii < 4; ii++)
#pragma unroll
                for (int jj = 0; jj < 8; jj++) acc[ii][jj] += ar[ii]*br[jj];
        }
        __syncthreads();
    }
#pragma unroll
    for (int ii = 0; ii < 4; ii++) {
        int oc = oc0 + ii;
        if (oc < 18) {
            float bb = pb[oc];
#pragma unroll
            for (int jj = 0; jj < 8; jj++)
                g_offb[(size_t)(b*18 + oc)*HW + hw0 + px0 + jj] = acc[ii][jj] + bb;
        } else if (oc < 27) {
            float bb = mb[oc - 18];
#pragma unroll
            for (int jj = 0; jj < 8; jj++)
                g_mb[(size_t)(b*9 + oc - 18)*HW + hw0 + px0 + jj] =
                    1.f / (1.f + expf(-(acc[ii][jj] + bb)));
        }
    }
}

// ---------------- K5: fused meta + sampling + deform GEMM -------------------
// 256 blocks of 128 px; 256 thr; tile 128oc x 128px, thread 8x8; chunk 2 ic
__global__ __launch_bounds__(256) void k_dgemm() {
    extern __shared__ char dyn[];
    int4*   si = (int4*)dyn;                 // [9*128]
    float4* sw = (float4*)(si + 1152);       // [9*128]
    float*  Ws = (float*)(sw + 1152);        // [18*132]
    float*  Vs = Ws + 18*132;                // [18*128]

    int tid  = threadIdx.x;
    int pxg0 = blockIdx.x * 128;
    int b    = pxg0 >> 12;
    int hw0  = pxg0 & 4095;
    int oc0  = (tid >> 4) * 8;
    int px0  = (tid & 15) * 8;

    // ---- sampling metadata for this block's 128 pixels x 9 taps ----
    for (int e = tid; e < 1152; e += 256) {
        int n = e >> 7, h = e & 127;
        int hw = hw0 + h;
        int r = hw >> 6, c = hw & 63;
        float ox = g_offb[(size_t)(b*18 + n)*HW + hw];
        float oy = g_offb[(size_t)(b*18 + 9 + n)*HW + hw];
        float px = (float)(r + 1) + (float)(n/3 - 1) + ox;
        float py = (float)(c + 1) + (float)(n%3 - 1) + oy;
        float fx = floorf(px), fy = floorf(py);
        float qx0 = fminf(fmaxf(fx,       0.f), 65.f);
        float qx1 = fminf(fmaxf(fx + 1.f, 0.f), 65.f);
        float qy0 = fminf(fmaxf(fy,       0.f), 65.f);
        float qy1 = fminf(fmaxf(fy + 1.f, 0.f), 65.f);
        float pxc = fminf(fmaxf(px, 0.f), 65.f);
        float pyc = fminf(fmaxf(py, 0.f), 65.f);
        float glt = (1.f + (qx0 - pxc)) * (1.f + (qy0 - pyc));
        float grb = (1.f - (qx1 - pxc)) * (1.f - (qy1 - pyc));
        float glb = (1.f + (qx0 - pxc)) * (1.f - (qy1 - pyc));
        float grt = (1.f - (qx1 - pxc)) * (1.f + (qy0 - pyc));
        float mod = g_mb[(size_t)(b*9 + n)*HW + hw];
        int ix0 = (int)qx0, ix1 = (int)qx1, iy0 = (int)qy0, iy1 = (int)qy1;
#define ENC(qx,qy) (((qx)>=1 && (qx)<=64 && (qy)>=1 && (qy)<=64) ? (((qx)-1)*64 + ((qy)-1)) : -1)
        si[e] = make_int4(ENC(ix0,iy0), ENC(ix1,iy1), ENC(ix0,iy1), ENC(ix1,iy0));
#undef ENC
        sw[e] = make_float4(glt*mod, grb*mod, glb*mod, grt*mod);
    }
    __syncthreads();

    float acc[8][8];
#pragma unroll
    for (int ii = 0; ii < 8; ii++)
#pragma unroll
        for (int jj = 0; jj < 8; jj++) acc[ii][jj] = 0.f;

    for (int ic0 = 0; ic0 < CH; ic0 += 2) {
        // stage weights (2304 elems)
        for (int e = tid; e < 2304; e += 256) {
            int kk = e >> 7, oc = e & 127;
            Ws[kk*132 + oc] = g_wT[(ic0*9 + kk)*CH + oc];
        }
        // stage sampled B tile (2304 elems, 4 gathers each)
        for (int e = tid; e < 2304; e += 256) {
            int kk = e >> 7, h = e & 127;
            int ic = ic0 + (kk >= 9 ? 1 : 0);
            int m  = (kk >= 9 ? kk - 9 : kk)*128 + h;
            int4   id = si[m];
            float4 w  = sw[m];
            const float* img = g_h + (size_t)(b*CH + ic)*HW;
            float v = 0.f;
            if (id.x >= 0) v += w.x * img[id.x];
            if (id.y >= 0) v += w.y * img[id.y];
            if (id.z >= 0) v += w.z * img[id.z];
            if (id.w >= 0) v += w.w * img[id.w];
            Vs[kk*128 + h] = v;
        }
        __syncthreads();
#pragma unroll
        for (int kk = 0; kk < 18; kk++) {
            float4 a0 = *(const float4*)&Ws[kk*132 + oc0];
            float4 a1 = *(const float4*)&Ws[kk*132 + oc0 + 4];
            float4 b0 = *(const float4*)&Vs[kk*128 + px0];
            float4 b1 = *(const float4*)&Vs[kk*128 + px0 + 4];
            float ar[8] = {a0.x,a0.y,a0.z,a0.w,a1.x,a1.y,a1.z,a1.w};
            float br[8] = {b0.x,b0.y,b0.z,b0.w,b1.x,b1.y,b1.z,b1.w};
#pragma unroll
            for (int ii = 0; ii < 8; ii++)
#pragma unroll
                for (int jj = 0; jj < 8; jj++) acc[ii][jj] += ar[ii]*br[jj];
        }
        __syncthreads();
    }
#pragma unroll
    for (int ii = 0; ii < 8; ii++)
#pragma unroll
        for (int jj = 0; jj < 8; jj++)
            g_d[(size_t)(b*CH + oc0 + ii)*HW + hw0 + px0 + jj] = acc[ii][jj];
}

// ---------------- stats: per-channel mean / rstd over (B,H,W) --------------
__global__ __launch_bounds__(256) void k_stats(const float* __restrict__ src,
                                               float* __restrict__ dst) {
    __shared__ float ss[256], sq[256];
    int ch = blockIdx.x, tid = threadIdx.x;
    float s = 0.f, s2 = 0.f;
    for (int i = tid; i < BB*HW; i += 256) {
        int b = i >> 12, hw = i & 4095;
        float v = src[(size_t)(b*CH + ch)*HW + hw];
        s += v; s2 += v*v;
    }
    ss[tid] = s; sq[tid] = s2;
    __syncthreads();
    for (int o = 128; o > 0; o >>= 1) {
        if (tid < o) { ss[tid] += ss[tid+o]; sq[tid] += sq[tid+o]; }
        __syncthreads();
    }
    if (tid == 0) {
        float mean = ss[0] * (1.f/32768.f);
        float var  = sq[0] * (1.f/32768.f) - mean*mean;
        dst[ch]      = mean;
        dst[CH + ch] = rsqrtf(var + 1e-5f);
    }
}

// ---------------- K7a: bn1 + exact gelu ------------------------------------
__global__ __launch_bounds__(256) void k_bn1gelu(const float* __restrict__ g,
                                                 const float* __restrict__ bv) {
    int i = blockIdx.x * 256 + threadIdx.x;
    if (i >= BB*CH*HW) return;
    int ch = (i >> 12) & (CH-1);
    float xn = (g_d[i] - g_s1[ch]) * g_s1[CH+ch] * g[ch] + bv[ch];
    g_t[i] = 0.5f * xn * (1.f + erff(xn * 0.70710678118654752f));
}

// ---------------- K7b: depthwise2 3x3 + bias --------------------------------
__global__ __launch_bounds__(256) void k_dw2(const float* __restrict__ w,
                                             const float* __restrict__ bias) {
    int i = blockIdx.x * 256 + threadIdx.x;
    if (i >= BB*CH*HW) return;
    int hw = i & (HW-1);
    int ch = (i >> 12) & (CH-1);
    int b  = i >> 19;
    int r = hw >> 6, c = hw & 63;
    const float* img = g_t + (size_t)(b*CH + ch)*HW;
    const float* wc  = w + ch*9;
    float acc = bias[ch];
#pragma unroll
    for (int dy = -1; dy <= 1; dy++)
#pragma unroll
        for (int dx = -1; dx <= 1; dx++) {
            int rr = r + dy, cc = c + dx;
            if ((unsigned)rr < 64u && (unsigned)cc < 64u)
                acc += wc[(dy+1)*3 + (dx+1)] * img[rr*64 + cc];
        }
    g_u[i] = acc;
}

// ---------------- K9: bn2 + relu -> out -------------------------------------
__global__ __launch_bounds__(256) void k_bn2relu(const float* __restrict__ g,
                                                 const float* __restrict__ bv,
                                                 float* __restrict__ out) {
    int i = blockIdx.x * 256 + threadIdx.x;
    if (i >= BB*CH*HW) return;
    int ch = (i >> 12) & (CH-1);
    float xn = (g_u[i] - g_s2[ch]) * g_s2[CH+ch] * g[ch] + bv[ch];
    out[i] = fmaxf(xn, 0.f);
}

// ---------------- launch ----------------------------------------------------
extern "C" void kernel_launch(void* const* d_in, const int* in_sizes, int n_in,
                              void* d_out, int out_size) {
    const float* x1      = (const float*)d_in[0];
    const float* x2      = (const float*)d_in[1];
    const float* dw1_w   = (const float*)d_in[2];
    const float* dw1_b   = (const float*)d_in[3];
    const float* pw_w    = (const float*)d_in[4];
    const float* pw_b    = (const float*)d_in[5];
    const float* p_w     = (const float*)d_in[6];
    const float* p_b     = (const float*)d_in[7];
    const float* m_w     = (const float*)d_in[8];
    const float* m_b     = (const float*)d_in[9];
    const float* dcn_w   = (const float*)d_in[10];
    const float* bn1_g   = (const float*)d_in[11];
    const float* bn1_b   = (const float*)d_in[12];
    const float* dw2_w   = (const float*)d_in[13];
    const float* dw2_b   = (const float*)d_in[14];
    const float* bn2_g   = (const float*)d_in[15];
    const float* bn2_b   = (const float*)d_in[16];
    float* out = (float*)d_out;

    float *s1p, *s2p, *dp, *up;
    cudaGetSymbolAddress((void**)&s1p, g_s1);
    cudaGetSymbolAddress((void**)&s2p, g_s2);
    cudaGetSymbolAddress((void**)&dp,  g_d);
    cudaGetSymbolAddress((void**)&up,  g_u);

    const int smemDG = 1152*16*2 + (18*132 + 18*128)*4;  // 55584 B
    cudaFuncSetAttribute(k_dgemm, cudaFuncAttributeMaxDynamicSharedMemorySize, smemDG);

    k_prep <<<848, 256>>>(dcn_w, pw_w, p_w, m_w);
    k_upcat<<<(BB*CC*HW + 255)/256, 256>>>(x1, x2);
    k_dw1  <<<(BB*CC*HW + 255)/256, 256>>>(dw1_w, dw1_b);
    k_pw   <<<PP/128, 256>>>(pw_b);
    k_offmask<<<PP/128, 128>>>(p_b, m_b);
    k_dgemm<<<PP/128, 256, smemDG>>>();
    k_stats<<<CH, 256>>>(dp, s1p);
    k_bn1gelu<<<(BB*CH*HW + 255)/256, 256>>>(bn1_g, bn1_b);
    k_dw2  <<<(BB*CH*HW + 255)/256, 256>>>(dw2_w, dw2_b);
    k_stats<<<CH, 256>>>(up, s2p);
    k_bn2relu<<<(BB*CH*HW + 255)/256, 256>>>(bn2_g, bn2_b, out);
}

// round 3
// speedup vs baseline: 1.3979x; 1.3282x over previous
#include <cuda_runtime.h>
#include <math.h>

#define BB 8
#define CH 128
#define CC 256
#define HW 4096
#define PP 32768      // BB*HW
#define KBIG 1152     // 128 ic * 9 taps

// ---------------- scratch (static device globals; no runtime alloc) --------
static __device__ float  g_x  [BB*CC*HW];     // concat(x2, up(x1))
static __device__ float  g_h1 [BB*CC*HW];     // depthwise1 out
static __device__ float  g_h  [BB*CH*HW];     // pointwise out
static __device__ float  g_offb[BB*18*HW];    // offsets
static __device__ float  g_mb [BB*9*HW];      // modulation (sigmoid)
static __device__ float  g_d  [BB*CH*HW];     // deform conv out
static __device__ float  g_t  [BB*CH*HW];     // gelu(bn1) out
static __device__ float  g_u  [BB*CH*HW];     // depthwise2 out
static __device__ float  g_s1 [2*CH];         // bn1 mean / rstd
static __device__ float  g_s2 [2*CH];         // bn2 mean / rstd
static __device__ float  g_wT  [KBIG*CH];     // dcn_w transposed [k][oc]
static __device__ float  g_pwT [CC*CH];       // pw_w transposed  [k][oc]
static __device__ float  g_omwT[KBIG*32];     // offset+mask w    [k][oc32]

// ---------------- K0: weight transposes -------------------------------------
__global__ __launch_bounds__(256) void k_prep(const float* __restrict__ dcn_w,
                                              const float* __restrict__ pw_w,
                                              const float* __restrict__ p_w,
                                              const float* __restrict__ m_w) {
    int i = blockIdx.x * 256 + threadIdx.x;
    if (i < KBIG*CH) {
        int k = i >> 7, oc = i & 127;
        g_wT[i] = dcn_w[oc*KBIG + k];
        return;
    }
    i -= KBIG*CH;
    if (i < CC*CH) {
        int k = i >> 7, oc = i & 127;
        g_pwT[i] = pw_w[oc*CC + k];
        return;
    }
    i -= CC*CH;
    if (i < KBIG*32) {
        int k = i >> 5, oc = i & 31;
        float v = 0.f;
        if (oc < 18)      v = p_w[oc*KBIG + k];
        else if (oc < 27) v = m_w[(oc-18)*KBIG + k];
        g_omwT[i] = v;
    }
}

// ---------------- K1: bilinear up2x (align_corners) + concat ---------------
__global__ __launch_bounds__(256) void k_upcat(const float* __restrict__ x1,
                                               const float* __restrict__ x2) {
    int i = blockIdx.x * 256 + threadIdx.x;
    if (i >= BB*CC*HW) return;
    int hw = i & (HW-1);
    int ch = (i >> 12) & (CC-1);
    int b  = i >> 20;
    float v;
    if (ch < CH) {
        v = x2[(b*CH + ch)*HW + hw];
    } else {
        int c1 = ch - CH;
        int r = hw >> 6, c = hw & 63;
        float sr = (float)r * (31.0f/63.0f);
        float sc = (float)c * (31.0f/63.0f);
        int i0 = min((int)floorf(sr), 30);
        int j0 = min((int)floorf(sc), 30);
        float ty = sr - (float)i0;
        float tx = sc - (float)j0;
        const float* img = x1 + ((size_t)(b*CH + c1))*1024;
        float a00 = img[i0*32 + j0],     a10 = img[(i0+1)*32 + j0];
        float a01 = img[i0*32 + j0 + 1], a11 = img[(i0+1)*32 + j0 + 1];
        v = (a00*(1.f-ty) + a10*ty)*(1.f-tx) + (a01*(1.f-ty) + a11*ty)*tx;
    }
    g_x[i] = v;
}

// ---------------- K2: depthwise 3x3 (256 ch) + bias ------------------------
__global__ __launch_bounds__(256) void k_dw1(const float* __restrict__ w,
                                             const float* __restrict__ bias) {
    int i = blockIdx.x * 256 + threadIdx.x;
    if (i >= BB*CC*HW) return;
    int hw = i & (HW-1);
    int ch = (i >> 12) & (CC-1);
    int b  = i >> 20;
    int r = hw >> 6, c = hw & 63;
    const float* img = g_x + (size_t)(b*CC + ch)*HW;
    const float* wc  = w + ch*9;
    float acc = bias[ch];
#pragma unroll
    for (int dy = -1; dy <= 1; dy++)
#pragma unroll
        for (int dx = -1; dx <= 1; dx++) {
            int rr = r + dy, cc = c + dx;
            if ((unsigned)rr < 64u && (unsigned)cc < 64u)
                acc += wc[(dy+1)*3 + (dx+1)] * img[rr*64 + cc];
        }
    g_h1[i] = acc;
}

// ---------------- K3: pointwise 256->128 GEMM, pipelined --------------------
// 128oc x 128px tile, 256 thr, 8x8 thread tile, K-chunk 16, double buffered
__global__ __launch_bounds__(256, 2) void k_pw(const float* __restrict__ bias) {
    __shared__ float Ws[2][16*132];
    __shared__ float Vs[2][16*128];
    int tid  = threadIdx.x;
    int pxg0 = blockIdx.x * 128;
    int b    = pxg0 >> 12;
    int hw0  = pxg0 & 4095;
    int oc0  = (tid >> 4) * 8;
    int px0  = (tid & 15) * 8;

    // stage chunk 0
#pragma unroll
    for (int i = 0; i < 8; i++) {
        int e = tid + i*256;
        int kk = e >> 7, oc = e & 127;
        Ws[0][kk*132 + oc] = g_pwT[kk*CH + oc];
    }
#pragma unroll
    for (int i = 0; i < 8; i++) {
        int e = tid + i*256;
        int kk = e >> 7, j = e & 127;
        Vs[0][kk*128 + j] = g_h1[(size_t)(b*CC + kk)*HW + hw0 + j];
    }
    __syncthreads();

    float acc[8][8];
#pragma unroll
    for (int ii = 0; ii < 8; ii++)
#pragma unroll
        for (int jj = 0; jj < 8; jj++) acc[ii][jj] = 0.f;

    for (int kc = 0; kc < 16; kc++) {
        int p = kc & 1;
        float wpre[8], vpre[8];
        if (kc < 15) {
            int k0 = (kc + 1) * 16;
#pragma unroll
            for (int i = 0; i < 8; i++) {
                int e = tid + i*256;
                int kk = e >> 7, oc = e & 127;
                wpre[i] = g_pwT[(k0 + kk)*CH + oc];
            }
#pragma unroll
            for (int i = 0; i < 8; i++) {
                int e = tid + i*256;
                int kk = e >> 7, j = e & 127;
                vpre[i] = g_h1[(size_t)(b*CC + k0 + kk)*HW + hw0 + j];
            }
        }
#pragma unroll
        for (int kk = 0; kk < 16; kk++) {
            float4 a0 = *(const float4*)&Ws[p][kk*132 + oc0];
            float4 a1 = *(const float4*)&Ws[p][kk*132 + oc0 + 4];
            float4 b0 = *(const float4*)&Vs[p][kk*128 + px0];
            float4 b1 = *(const float4*)&Vs[p][kk*128 + px0 + 4];
            float ar[8] = {a0.x,a0.y,a0.z,a0.w,a1.x,a1.y,a1.z,a1.w};
            float br[8] = {b0.x,b0.y,b0.z,b0.w,b1.x,b1.y,b1.z,b1.w};
#pragma unroll
            for (int ii = 0; ii < 8; ii++)
#pragma unroll
                for (int jj = 0; jj < 8; jj++) acc[ii][jj] += ar[ii]*br[jj];
        }
        if (kc < 15) {
#pragma unroll
            for (int i = 0; i < 8; i++) {
                int e = tid + i*256;
                int kk = e >> 7, oc = e & 127;
                Ws[1-p][kk*132 + oc] = wpre[i];
            }
#pragma unroll
            for (int i = 0; i < 8; i++) {
                int e = tid + i*256;
                int kk = e >> 7, j = e & 127;
                Vs[1-p][kk*128 + j] = vpre[i];
            }
        }
        __syncthreads();
    }
#pragma unroll
    for (int ii = 0; ii < 8; ii++) {
        float bb = bias[oc0 + ii];
#pragma unroll
        for (int jj = 0; jj < 8; jj++)
            g_h[(size_t)(b*CH + oc0 + ii)*HW + hw0 + px0 + jj] = acc[ii][jj] + bb;
    }
}

// ---------------- K4: offset(18)+mask(9) conv as GEMM, pipelined ------------
// 32oc x 128px tile, 256 thr, 4oc x 4px thread tile, K-chunk 18 (2 ic)
__global__ __launch_bounds__(256) void k_offmask(const float* __restrict__ pb,
                                                 const float* __restrict__ mb) {
    __shared__ float Ws[2][18*36];
    __shared__ float Vs[2][18*128];
    __shared__ int   noff[9*128];
    int tid  = threadIdx.x;
    int pxg0 = blockIdx.x * 128;
    int b    = pxg0 >> 12;
    int hw0  = pxg0 & 4095;
    int oc0  = (tid >> 5) * 4;   // 8 groups x 4 oc = 32
    int px0  = (tid & 31) * 4;   // 32 groups x 4 px = 128

    for (int e = tid; e < 1152; e += 256) {
        int t = e >> 7, h = e & 127;
        int hw = hw0 + h;
        int r = hw >> 6, c = hw & 63;
        int dy = t/3 - 1, dx = t%3 - 1;
        int rr = r + dy, cc = c + dx;
        noff[e] = ((unsigned)rr < 64u && (unsigned)cc < 64u) ? (rr*64 + cc) : -1;
    }
    __syncthreads();

    // stage chunk 0 (ic0 = 0)
#pragma unroll
    for (int i = 0; i < 3; i++) {
        int e = tid + i*256;
        if (e < 576) {
            int kk = e >> 5, oc = e & 31;
            Ws[0][kk*36 + oc] = g_omwT[kk*32 + oc];
        }
    }
#pragma unroll
    for (int i = 0; i < 9; i++) {
        int e = tid + i*256;
        int kk = e >> 7, h = e & 127;
        int ic = (kk >= 9 ? 1 : 0);
        int t  = kk >= 9 ? kk - 9 : kk;
        int idx = noff[t*128 + h];
        const float* img = g_h + (size_t)(b*CH + ic)*HW;
        Vs[0][kk*128 + h] = (idx >= 0) ? img[idx] : 0.f;
    }
    __syncthreads();

    float acc[4][4];
#pragma unroll
    for (int ii = 0; ii < 4; ii++)
#pragma unroll
        for (int jj = 0; jj < 4; jj++) acc[ii][jj] = 0.f;

    for (int kc = 0; kc < 64; kc++) {
        int p = kc & 1;
        float wpre[3], vpre[9];
        if (kc < 63) {
            int ic0 = (kc + 1) * 2;
#pragma unroll
            for (int i = 0; i < 3; i++) {
                int e = tid + i*256;
                wpre[i] = (e < 576) ? g_omwT[(ic0*9 + (e >> 5))*32 + (e & 31)] : 0.f;
            }
#pragma unroll
            for (int i = 0; i < 9; i++) {
                int e = tid + i*256;
                int kk = e >> 7, h = e & 127;
                int ic = ic0 + (kk >= 9 ? 1 : 0);
                int t  = kk >= 9 ? kk - 9 : kk;
                int idx = noff[t*128 + h];
                const float* img = g_h + (size_t)(b*CH + ic)*HW;
                vpre[i] = (idx >= 0) ? img[idx] : 0.f;
            }
        }
#pragma unroll
        for (int kk = 0; kk < 18; kk++) {
            float4 a0 = *(const float4*)&Ws[p][kk*36 + oc0];
            float4 b0 = *(const float4*)&Vs[p][kk*128 + px0];
            float ar[4] = {a0.x,a0.y,a0.z,a0.w};
            float br[4] = {b0.x,b0.y,b0.z,b0.w};
#pragma unroll
            for (int ii = 0; ii < 4; ii++)
#pragma unroll
                for (int jj = 0; jj < 4; jj++) acc[ii][jj] += ar[ii]*br[jj];
        }
        if (kc < 63) {
#pragma unroll
            for (int i = 0; i < 3; i++) {
                int e = tid + i*256;
                if (e < 576) Ws[1-p][(e >> 5)*36 + (e & 31)] = wpre[i];
            }
#pragma unroll
            for (int i = 0; i < 9; i++) {
                int e = tid + i*256;
                Vs[1-p][(e >> 7)*128 + (e & 127)] = vpre[i];
            }
        }
        __syncthreads();
    }
#pragma unroll
    for (int ii = 0; ii < 4; ii++) {
        int oc = oc0 + ii;
        if (oc < 18) {
            float bb = pb[oc];
#pragma unroll
            for (int jj = 0; jj < 4; jj++)
                g_offb[(size_t)(b*18 + oc)*HW + hw0 + px0 + jj] = acc[ii][jj] + bb;
        } else if (oc < 27) {
            float bb = mb[oc - 18];
#pragma unroll
            for (int jj = 0; jj < 4; jj++)
                g_mb[(size_t)(b*9 + oc - 18)*HW + hw0 + px0 + jj] =
                    1.f / (1.f + expf(-(acc[ii][jj] + bb)));
        }
    }
}

// ---------------- K5: fused meta + sampling + deform GEMM, pipelined --------
// 128oc x 128px tile, 256 thr, 8x8 thread tile, K-chunk 18 (2 ic), dbl-buf
__global__ __launch_bounds__(256) void k_dgemm() {
    extern __shared__ char dyn[];
    int4*   si = (int4*)dyn;                 // [9*128]
    float4* sw = (float4*)(si + 1152);       // [9*128]
    float*  Ws = (float*)(sw + 1152);        // [2][18*132]
    float*  Vs = Ws + 2*18*132;              // [2][18*128]

    int tid  = threadIdx.x;
    int pxg0 = blockIdx.x * 128;
    int b    = pxg0 >> 12;
    int hw0  = pxg0 & 4095;
    int oc0  = (tid >> 4) * 8;
    int px0  = (tid & 15) * 8;

    // ---- sampling metadata for this block's 128 pixels x 9 taps ----
    for (int e = tid; e < 1152; e += 256) {
        int n = e >> 7, h = e & 127;
        int hw = hw0 + h;
        int r = hw >> 6, c = hw & 63;
        float ox = g_offb[(size_t)(b*18 + n)*HW + hw];
        float oy = g_offb[(size_t)(b*18 + 9 + n)*HW + hw];
        float px = (float)(r + 1) + (float)(n/3 - 1) + ox;
        float py = (float)(c + 1) + (float)(n%3 - 1) + oy;
        float fx = floorf(px), fy = floorf(py);
        float qx0 = fminf(fmaxf(fx,       0.f), 65.f);
        float qx1 = fminf(fmaxf(fx + 1.f, 0.f), 65.f);
        float qy0 = fminf(fmaxf(fy,       0.f), 65.f);
        float qy1 = fminf(fmaxf(fy + 1.f, 0.f), 65.f);
        float pxc = fminf(fmaxf(px, 0.f), 65.f);
        float pyc = fminf(fmaxf(py, 0.f), 65.f);
        float glt = (1.f + (qx0 - pxc)) * (1.f + (qy0 - pyc));
        float grb = (1.f - (qx1 - pxc)) * (1.f - (qy1 - pyc));
        float glb = (1.f + (qx0 - pxc)) * (1.f - (qy1 - pyc));
        float grt = (1.f - (qx1 - pxc)) * (1.f + (qy0 - pyc));
        float mod = g_mb[(size_t)(b*9 + n)*HW + hw];
        int ix0 = (int)qx0, ix1 = (int)qx1, iy0 = (int)qy0, iy1 = (int)qy1;
#define ENC(qx,qy) (((qx)>=1 && (qx)<=64 && (qy)>=1 && (qy)<=64) ? (((qx)-1)*64 + ((qy)-1)) : -1)
        si[e] = make_int4(ENC(ix0,iy0), ENC(ix1,iy1), ENC(ix0,iy1), ENC(ix1,iy0));
#undef ENC
        sw[e] = make_float4(glt*mod, grb*mod, glb*mod, grt*mod);
    }
    __syncthreads();

    // stage chunk 0 (ic0 = 0)
#pragma unroll
    for (int i = 0; i < 9; i++) {
        int e = tid + i*256;
        int kk = e >> 7, oc = e & 127;
        Ws[kk*132 + oc] = g_wT[kk*CH + oc];
    }
#pragma unroll
    for (int i = 0; i < 9; i++) {
        int e = tid + i*256;
        int kk = e >> 7, h = e & 127;
        int ic = (kk >= 9 ? 1 : 0);
        int m  = (kk >= 9 ? kk - 9 : kk)*128 + h;
        int4   id = si[m];
        float4 w  = sw[m];
        const float* img = g_h + (size_t)(b*CH + ic)*HW;
        float v = 0.f;
        if (id.x >= 0) v += w.x * img[id.x];
        if (id.y >= 0) v += w.y * img[id.y];
        if (id.z >= 0) v += w.z * img[id.z];
        if (id.w >= 0) v += w.w * img[id.w];
        Vs[kk*128 + h] = v;
    }
    __syncthreads();

    float acc[8][8];
#pragma unroll
    for (int ii = 0; ii < 8; ii++)
#pragma unroll
        for (int jj = 0; jj < 8; jj++) acc[ii][jj] = 0.f;

    for (int kc = 0; kc < 64; kc++) {
        int p = kc & 1;
        float* Wsp = Ws + p*(18*132);
        float* Vsp = Vs + p*(18*128);
        float wpre[9], vpre[9];
        if (kc < 63) {
            int ic0 = (kc + 1) * 2;
#pragma unroll
            for (int i = 0; i < 9; i++) {
                int e = tid + i*256;
                int kk = e >> 7, oc = e & 127;
                wpre[i] = g_wT[(ic0*9 + kk)*CH + oc];
            }
#pragma unroll
            for (int i = 0; i < 9; i++) {
                int e = tid + i*256;
                int kk = e >> 7, h = e & 127;
                int ic = ic0 + (kk >= 9 ? 1 : 0);
                int m  = (kk >= 9 ? kk - 9 : kk)*128 + h;
                int4   id = si[m];
                float4 w  = sw[m];
                const float* img = g_h + (size_t)(b*CH + ic)*HW;
                float v = 0.f;
                if (id.x >= 0) v += w.x * img[id.x];
                if (id.y >= 0) v += w.y * img[id.y];
                if (id.z >= 0) v += w.z * img[id.z];
                if (id.w >= 0) v += w.w * img[id.w];
                vpre[i] = v;
            }
        }
#pragma unroll
        for (int kk = 0; kk < 18; kk++) {
            float4 a0 = *(const float4*)&Wsp[kk*132 + oc0];
            float4 a1 = *(const float4*)&Wsp[kk*132 + oc0 + 4];
            float4 b0 = *(const float4*)&Vsp[kk*128 + px0];
            float4 b1 = *(const float4*)&Vsp[kk*128 + px0 + 4];
            float ar[8] = {a0.x,a0.y,a0.z,a0.w,a1.x,a1.y,a1.z,a1.w};
            float br[8] = {b0.x,b0.y,b0.z,b0.w,b1.x,b1.y,b1.z,b1.w};
#pragma unroll
            for (int ii = 0; ii < 8; ii++)
#pragma unroll
                for (int jj = 0; jj < 8; jj++) acc[ii][jj] += ar[ii]*br[jj];
        }
        if (kc < 63) {
            float* Wsn = Ws + (1-p)*(18*132);
            float* Vsn = Vs + (1-p)*(18*128);
#pragma unroll
            for (int i = 0; i < 9; i++) {
                int e = tid + i*256;
                Wsn[(e >> 7)*132 + (e & 127)] = wpre[i];
            }
#pragma unroll
            for (int i = 0; i < 9; i++) {
                int e = tid + i*256;
                Vsn[(e >> 7)*128 + (e & 127)] = vpre[i];
            }
        }
        __syncthreads();
    }
#pragma unroll
    for (int ii = 0; ii < 8; ii++)
#pragma unroll
        for (int jj = 0; jj < 8; jj++)
            g_d[(size_t)(b*CH + oc0 + ii)*HW + hw0 + px0 + jj] = acc[ii][jj];
}

// ---------------- stats: per-channel mean / rstd over (B,H,W) --------------
__global__ __launch_bounds__(256) void k_stats(const float* __restrict__ src,
                                               float* __restrict__ dst) {
    __shared__ float ss[256], sq[256];
    int ch = blockIdx.x, tid = threadIdx.x;
    float s = 0.f, s2 = 0.f;
    for (int i = tid; i < BB*HW; i += 256) {
        int b = i >> 12, hw = i & 4095;
        float v = src[(size_t)(b*CH + ch)*HW + hw];
        s += v; s2 += v*v;
    }
    ss[tid] = s; sq[tid] = s2;
    __syncthreads();
    for (int o = 128; o > 0; o >>= 1) {
        if (tid < o) { ss[tid] += ss[tid+o]; sq[tid] += sq[tid+o]; }
        __syncthreads();
    }
    if (tid == 0) {
        float mean = ss[0] * (1.f/32768.f);
        float var  = sq[0] * (1.f/32768.f) - mean*mean;
        dst[ch]      = mean;
        dst[CH + ch] = rsqrtf(var + 1e-5f);
    }
}

// ---------------- K7a: bn1 + exact gelu ------------------------------------
__global__ __launch_bounds__(256) void k_bn1gelu(const float* __restrict__ g,
                                                 const float* __restrict__ bv) {
    int i = blockIdx.x * 256 + threadIdx.x;
    if (i >= BB*CH*HW) return;
    int ch = (i >> 12) & (CH-1);
    float xn = (g_d[i] - g_s1[ch]) * g_s1[CH+ch] * g[ch] + bv[ch];
    g_t[i] = 0.5f * xn * (1.f + erff(xn * 0.70710678118654752f));
}

// ---------------- K7b: depthwise2 3x3 + bias --------------------------------
__global__ __launch_bounds__(256) void k_dw2(const float* __restrict__ w,
                                             const float* __restrict__ bias) {
    int i = blockIdx.x * 256 + threadIdx.x;
    if (i >= BB*CH*HW) return;
    int hw = i & (HW-1);
    int ch = (i >> 12) & (CH-1);
    int b  = i >> 19;
    int r = hw >> 6, c = hw & 63;
    const float* img = g_t + (size_t)(b*CH + ch)*HW;
    const float* wc  = w + ch*9;
    float acc = bias[ch];
#pragma unroll
    for (int dy = -1; dy <= 1; dy++)
#pragma unroll
        for (int dx = -1; dx <= 1; dx++) {
            int rr = r + dy, cc = c + dx;
            if ((unsigned)rr < 64u && (unsigned)cc < 64u)
                acc += wc[(dy+1)*3 + (dx+1)] * img[rr*64 + cc];
        }
    g_u[i] = acc;
}

// ---------------- K9: bn2 + relu -> out -------------------------------------
__global__ __launch_bounds__(256) void k_bn2relu(const float* __restrict__ g,
                                                 const float* __restrict__ bv,
                                                 float* __restrict__ out) {
    int i = blockIdx.x * 256 + threadIdx.x;
    if (i >= BB*CH*HW) return;
    int ch = (i >> 12) & (CH-1);
    float xn = (g_u[i] - g_s2[ch]) * g_s2[CH+ch] * g[ch] + bv[ch];
    out[i] = fmaxf(xn, 0.f);
}

// ---------------- launch ----------------------------------------------------
extern "C" void kernel_launch(void* const* d_in, const int* in_sizes, int n_in,
                              void* d_out, int out_size) {
    const float* x1      = (const float*)d_in[0];
    const float* x2      = (const float*)d_in[1];
    const float* dw1_w   = (const float*)d_in[2];
    const float* dw1_b   = (const float*)d_in[3];
    const float* pw_w    = (const float*)d_in[4];
    const float* pw_b    = (const float*)d_in[5];
    const float* p_w     = (const float*)d_in[6];
    const float* p_b     = (const float*)d_in[7];
    const float* m_w     = (const float*)d_in[8];
    const float* m_b     = (const float*)d_in[9];
    const float* dcn_w   = (const float*)d_in[10];
    const float* bn1_g   = (const float*)d_in[11];
    const float* bn1_b   = (const float*)d_in[12];
    const float* dw2_w   = (const float*)d_in[13];
    const float* dw2_b   = (const float*)d_in[14];
    const float* bn2_g   = (const float*)d_in[15];
    const float* bn2_b   = (const float*)d_in[16];
    float* out = (float*)d_out;

    float *s1p, *s2p, *dp, *up;
    cudaGetSymbolAddress((void**)&s1p, g_s1);
    cudaGetSymbolAddress((void**)&s2p, g_s2);
    cudaGetSymbolAddress((void**)&dp,  g_d);
    cudaGetSymbolAddress((void**)&up,  g_u);

    const int smemDG = 1152*16*2 + (2*18*132 + 2*18*128)*4;  // 74304 B
    cudaFuncSetAttribute(k_dgemm, cudaFuncAttributeMaxDynamicSharedMemorySize, smemDG);

    k_prep <<<848, 256>>>(dcn_w, pw_w, p_w, m_w);
    k_upcat<<<(BB*CC*HW + 255)/256, 256>>>(x1, x2);
    k_dw1  <<<(BB*CC*HW + 255)/256, 256>>>(dw1_w, dw1_b);
    k_pw   <<<PP/128, 256>>>(pw_b);
    k_offmask<<<PP/128, 256>>>(p_b, m_b);
    k_dgemm<<<PP/128, 256, smemDG>>>();
    k_stats<<<CH, 256>>>(dp, s1p);
    k_bn1gelu<<<(BB*CH*HW + 255)/256, 256>>>(bn1_g, bn1_b);
    k_dw2  <<<(BB*CH*HW + 255)/256, 256>>>(dw2_w, dw2_b);
    k_stats<<<CH, 256>>>(up, s2p);
    k_bn2relu<<<(BB*CH*HW + 255)/256, 256>>>(bn2_g, bn2_b, out);
}

// round 5
// speedup vs baseline: 2.1365x; 1.5283x over previous
#include <cuda_runtime.h>
#include <cuda_bf16.h>
#include <math.h>
#include <cstdint>

#define BB 8
#define CH 128
#define CC 256
#define HW 4096
#define PP 32768      // BB*HW
#define KBIG 1152     // 128 ic * 9 taps

// ---------------- scratch (static device globals; no runtime alloc) --------
static __device__ float  g_x  [BB*CC*HW];     // concat(x2, up(x1))
static __device__ float  g_h1 [BB*CC*HW];     // depthwise1 out
static __device__ float  g_h  [BB*CH*HW];     // pointwise out
static __device__ float  g_offb[BB*18*HW];    // offsets
static __device__ float  g_mb [BB*9*HW];      // modulation (sigmoid)
static __device__ float  g_d  [BB*CH*HW];     // deform conv out
static __device__ float  g_t  [BB*CH*HW];     // gelu(bn1) out
static __device__ float  g_u  [BB*CH*HW];     // depthwise2 out
static __device__ float  g_s1 [2*CH];         // bn1 mean / rstd
static __device__ float  g_s2 [2*CH];         // bn2 mean / rstd
static __device__ float  g_pwT [CC*CH];       // pw_w transposed  [k][oc]
static __device__ float  g_omwT[KBIG*32];     // offset+mask w    [k][oc32]
// dcn weights: per chunk c (tap=c>>1, ichalf=c&1): hi tile (8192 bf16) then lo
// tile (8192 bf16), each pre-swizzled SW128 K-major 128oc x 64k
static __device__ __nv_bfloat16 g_wA[18*16384];

#define SW128(o)   ((o) ^ (((o) >> 3) & 0x70))

__device__ __forceinline__ uint32_t smem_u32(const void* p) {
    uint32_t a;
    asm("{ .reg .u64 t; cvta.to.shared.u64 t, %1; cvt.u32.u64 %0, t; }"
        : "=r"(a) : "l"(p));
    return a;
}
__device__ __forceinline__ void ldmx4(uint32_t* r, uint32_t addr) {
    asm volatile("ldmatrix.sync.aligned.m8n8.x4.shared.b16 {%0,%1,%2,%3}, [%4];"
                 : "=r"(r[0]), "=r"(r[1]), "=r"(r[2]), "=r"(r[3]) : "r"(addr));
}
__device__ __forceinline__ void mma_bf16(float* d, const uint32_t* a,
                                         uint32_t b0, uint32_t b1) {
    asm volatile("mma.sync.aligned.m16n8k16.row.col.f32.bf16.bf16.f32 "
                 "{%0,%1,%2,%3}, {%4,%5,%6,%7}, {%8,%9}, {%0,%1,%2,%3};"
                 : "+f"(d[0]), "+f"(d[1]), "+f"(d[2]), "+f"(d[3])
                 : "r"(a[0]), "r"(a[1]), "r"(a[2]), "r"(a[3]), "r"(b0), "r"(b1));
}

// ---------------- K0: weight prep -------------------------------------------
__global__ __launch_bounds__(256) void k_prep(const float* __restrict__ dcn_w,
                                              const float* __restrict__ pw_w,
                                              const float* __restrict__ p_w,
                                              const float* __restrict__ m_w) {
    int i = blockIdx.x * 256 + threadIdx.x;
    if (i < 18*16384) {
        int c = i >> 14;
        int r = i & 16383;
        int s = r >> 13;            // 0 hi, 1 lo
        int e = r & 8191;
        int oc = e >> 6, ic = e & 63;
        int tap = c >> 1, ichalf = c & 1;
        float val = dcn_w[oc*KBIG + (ichalf*64 + ic)*9 + tap];
        __nv_bfloat16 hi = __float2bfloat16(val);
        __nv_bfloat16 out = s ? __float2bfloat16(val - __bfloat162float(hi)) : hi;
        uint32_t off = SW128((uint32_t)(oc*128 + ic*2));
        g_wA[(size_t)c*16384 + s*8192 + (off >> 1)] = out;
        return;
    }
    i -= 18*16384;
    if (i < CC*CH) {
        int k = i >> 7, oc = i & 127;
        g_pwT[i] = pw_w[oc*CC + k];
        return;
    }
    i -= CC*CH;
    if (i < KBIG*32) {
        int k = i >> 5, oc = i & 31;
        float v = 0.f;
        if (oc < 18)      v = p_w[oc*KBIG + k];
        else if (oc < 27) v = m_w[(oc-18)*KBIG + k];
        g_omwT[i] = v;
    }
}

// ---------------- K1: bilinear up2x (align_corners) + concat ---------------
__global__ __launch_bounds__(256) void k_upcat(const float* __restrict__ x1,
                                               const float* __restrict__ x2) {
    int i = blockIdx.x * 256 + threadIdx.x;
    if (i >= BB*CC*HW) return;
    int hw = i & (HW-1);
    int ch = (i >> 12) & (CC-1);
    int b  = i >> 20;
    float v;
    if (ch < CH) {
        v = x2[(b*CH + ch)*HW + hw];
    } else {
        int c1 = ch - CH;
        int r = hw >> 6, c = hw & 63;
        float sr = (float)r * (31.0f/63.0f);
        float sc = (float)c * (31.0f/63.0f);
        int i0 = min((int)floorf(sr), 30);
        int j0 = min((int)floorf(sc), 30);
        float ty = sr - (float)i0;
        float tx = sc - (float)j0;
        const float* img = x1 + ((size_t)(b*CH + c1))*1024;
        float a00 = img[i0*32 + j0],     a10 = img[(i0+1)*32 + j0];
        float a01 = img[i0*32 + j0 + 1], a11 = img[(i0+1)*32 + j0 + 1];
        v = (a00*(1.f-ty) + a10*ty)*(1.f-tx) + (a01*(1.f-ty) + a11*ty)*tx;
    }
    g_x[i] = v;
}

// ---------------- K2: depthwise 3x3 (256 ch) + bias ------------------------
__global__ __launch_bounds__(256) void k_dw1(const float* __restrict__ w,
                                             const float* __restrict__ bias) {
    int i = blockIdx.x * 256 + threadIdx.x;
    if (i >= BB*CC*HW) return;
    int hw = i & (HW-1);
    int ch = (i >> 12) & (CC-1);
    int b  = i >> 20;
    int r = hw >> 6, c = hw & 63;
    const float* img = g_x + (size_t)(b*CC + ch)*HW;
    const float* wc  = w + ch*9;
    float acc = bias[ch];
#pragma unroll
    for (int dy = -1; dy <= 1; dy++)
#pragma unroll
        for (int dx = -1; dx <= 1; dx++) {
            int rr = r + dy, cc = c + dx;
            if ((unsigned)rr < 64u && (unsigned)cc < 64u)
                acc += wc[(dy+1)*3 + (dx+1)] * img[rr*64 + cc];
        }
    g_h1[i] = acc;
}

// ---------------- K3: pointwise 256->128 GEMM, pipelined --------------------
__global__ __launch_bounds__(256, 2) void k_pw(const float* __restrict__ bias) {
    __shared__ float Ws[2][16*132];
    __shared__ float Vs[2][16*128];
    int tid  = threadIdx.x;
    int pxg0 = blockIdx.x * 128;
    int b    = pxg0 >> 12;
    int hw0  = pxg0 & 4095;
    int oc0  = (tid >> 4) * 8;
    int px0  = (tid & 15) * 8;

#pragma unroll
    for (int i = 0; i < 8; i++) {
        int e = tid + i*256;
        Ws[0][(e >> 7)*132 + (e & 127)] = g_pwT[(e >> 7)*CH + (e & 127)];
    }
#pragma unroll
    for (int i = 0; i < 8; i++) {
        int e = tid + i*256;
        Vs[0][(e >> 7)*128 + (e & 127)] = g_h1[(size_t)(b*CC + (e >> 7))*HW + hw0 + (e & 127)];
    }
    __syncthreads();

    float acc[8][8];
#pragma unroll
    for (int ii = 0; ii < 8; ii++)
#pragma unroll
        for (int jj = 0; jj < 8; jj++) acc[ii][jj] = 0.f;

    for (int kc = 0; kc < 16; kc++) {
        int p = kc & 1;
        float wpre[8], vpre[8];
        if (kc < 15) {
            int k0 = (kc + 1) * 16;
#pragma unroll
            for (int i = 0; i < 8; i++) {
                int e = tid + i*256;
                wpre[i] = g_pwT[(k0 + (e >> 7))*CH + (e & 127)];
            }
#pragma unroll
            for (int i = 0; i < 8; i++) {
                int e = tid + i*256;
                vpre[i] = g_h1[(size_t)(b*CC + k0 + (e >> 7))*HW + hw0 + (e & 127)];
            }
        }
#pragma unroll
        for (int kk = 0; kk < 16; kk++) {
            float4 a0 = *(const float4*)&Ws[p][kk*132 + oc0];
            float4 a1 = *(const float4*)&Ws[p][kk*132 + oc0 + 4];
            float4 b0 = *(const float4*)&Vs[p][kk*128 + px0];
            float4 b1 = *(const float4*)&Vs[p][kk*128 + px0 + 4];
            float ar[8] = {a0.x,a0.y,a0.z,a0.w,a1.x,a1.y,a1.z,a1.w};
            float br[8] = {b0.x,b0.y,b0.z,b0.w,b1.x,b1.y,b1.z,b1.w};
#pragma unroll
            for (int ii = 0; ii < 8; ii++)
#pragma unroll
                for (int jj = 0; jj < 8; jj++) acc[ii][jj] += ar[ii]*br[jj];
        }
        if (kc < 15) {
#pragma unroll
            for (int i = 0; i < 8; i++) {
                int e = tid + i*256;
                Ws[1-p][(e >> 7)*132 + (e & 127)] = wpre[i];
            }
#pragma unroll
            for (int i = 0; i < 8; i++) {
                int e = tid + i*256;
                Vs[1-p][(e >> 7)*128 + (e & 127)] = vpre[i];
            }
        }
        __syncthreads();
    }
#pragma unroll
    for (int ii = 0; ii < 8; ii++) {
        float bb = bias[oc0 + ii];
#pragma unroll
        for (int jj = 0; jj < 8; jj++)
            g_h[(size_t)(b*CH + oc0 + ii)*HW + hw0 + px0 + jj] = acc[ii][jj] + bb;
    }
}

// ---------------- K4: offset(18)+mask(9) conv as GEMM, pipelined ------------
__global__ __launch_bounds__(256) void k_offmask(const float* __restrict__ pb,
                                                 const float* __restrict__ mb) {
    __shared__ float Ws[2][18*36];
    __shared__ float Vs[2][18*128];
    __shared__ int   noff[9*128];
    int tid  = threadIdx.x;
    int pxg0 = blockIdx.x * 128;
    int b    = pxg0 >> 12;
    int hw0  = pxg0 & 4095;
    int oc0  = (tid >> 5) * 4;
    int px0  = (tid & 31) * 4;

    for (int e = tid; e < 1152; e += 256) {
        int t = e >> 7, h = e & 127;
        int hw = hw0 + h;
        int r = hw >> 6, c = hw & 63;
        int dy = t/3 - 1, dx = t%3 - 1;
        int rr = r + dy, cc = c + dx;
        noff[e] = ((unsigned)rr < 64u && (unsigned)cc < 64u) ? (rr*64 + cc) : -1;
    }
    __syncthreads();

#pragma unroll
    for (int i = 0; i < 3; i++) {
        int e = tid + i*256;
        if (e < 576) Ws[0][(e >> 5)*36 + (e & 31)] = g_omwT[(e >> 5)*32 + (e & 31)];
    }
#pragma unroll
    for (int i = 0; i < 9; i++) {
        int e = tid + i*256;
        int kk = e >> 7, h = e & 127;
        int ic = (kk >= 9 ? 1 : 0);
        int t  = kk >= 9 ? kk - 9 : kk;
        int idx = noff[t*128 + h];
        const float* img = g_h + (size_t)(b*CH + ic)*HW;
        Vs[0][kk*128 + h] = (idx >= 0) ? img[idx] : 0.f;
    }
    __syncthreads();

    float acc[4][4];
#pragma unroll
    for (int ii = 0; ii < 4; ii++)
#pragma unroll
        for (int jj = 0; jj < 4; jj++) acc[ii][jj] = 0.f;

    for (int kc = 0; kc < 64; kc++) {
        int p = kc & 1;
        float wpre[3], vpre[9];
        if (kc < 63) {
            int ic0 = (kc + 1) * 2;
#pragma unroll
            for (int i = 0; i < 3; i++) {
                int e = tid + i*256;
                wpre[i] = (e < 576) ? g_omwT[(ic0*9 + (e >> 5))*32 + (e & 31)] : 0.f;
            }
#pragma unroll
            for (int i = 0; i < 9; i++) {
                int e = tid + i*256;
                int kk = e >> 7, h = e & 127;
                int ic = ic0 + (kk >= 9 ? 1 : 0);
                int t  = kk >= 9 ? kk - 9 : kk;
                int idx = noff[t*128 + h];
                const float* img = g_h + (size_t)(b*CH + ic)*HW;
                vpre[i] = (idx >= 0) ? img[idx] : 0.f;
            }
        }
#pragma unroll
        for (int kk = 0; kk < 18; kk++) {
            float4 a0 = *(const float4*)&Ws[p][kk*36 + oc0];
            float4 b0 = *(const float4*)&Vs[p][kk*128 + px0];
            float ar[4] = {a0.x,a0.y,a0.z,a0.w};
            float br[4] = {b0.x,b0.y,b0.z,b0.w};
#pragma unroll
            for (int ii = 0; ii < 4; ii++)
#pragma unroll
                for (int jj = 0; jj < 4; jj++) acc[ii][jj] += ar[ii]*br[jj];
        }
        if (kc < 63) {
#pragma unroll
            for (int i = 0; i < 3; i++) {
                int e = tid + i*256;
                if (e < 576) Ws[1-p][(e >> 5)*36 + (e & 31)] = wpre[i];
            }
#pragma unroll
            for (int i = 0; i < 9; i++) {
                int e = tid + i*256;
                Vs[1-p][(e >> 7)*128 + (e & 127)] = vpre[i];
            }
        }
        __syncthreads();
    }
#pragma unroll
    for (int ii = 0; ii < 4; ii++) {
        int oc = oc0 + ii;
        if (oc < 18) {
            float bb = pb[oc];
#pragma unroll
            for (int jj = 0; jj < 4; jj++)
                g_offb[(size_t)(b*18 + oc)*HW + hw0 + px0 + jj] = acc[ii][jj] + bb;
        } else if (oc < 27) {
            float bb = mb[oc - 18];
#pragma unroll
            for (int jj = 0; jj < 4; jj++)
                g_mb[(size_t)(b*9 + oc - 18)*HW + hw0 + px0 + jj] =
                    1.f / (1.f + expf(-(acc[ii][jj] + bb)));
        }
    }
}

// ---------------- K5: deform conv via mma.sync bf16x3 -----------------------
// CTA 128oc x 128px; 8 warps (2 oc x 4 px): warp 64oc x 32px.
// K = 1152 in 18 chunks of 64 (tap, ic-half); A/B hi+lo bf16 SW128 images.
// smem: si [0,18432), sw [18432,36864), tiles at 36864: 2 bufs x 64KB
//   buf p: Ahi +0, Alo +16384, Bhi +32768, Blo +49152
#define SM_SI    0
#define SM_SW    18432
#define SM_TILE  36864
#define SMEM_DG  (SM_TILE + 2*65536)

__device__ __forceinline__ float dsample(const float* img, int4 id, float4 w) {
    float v = 0.f;
    if (id.x >= 0) v += w.x * img[id.x];
    if (id.y >= 0) v += w.y * img[id.y];
    if (id.z >= 0) v += w.z * img[id.z];
    if (id.w >= 0) v += w.w * img[id.w];
    return v;
}

__global__ __launch_bounds__(256, 1) void k_dgemm_tc() {
    extern __shared__ __align__(1024) unsigned char smem[];
    uint32_t sb = smem_u32(smem);
    int tid  = threadIdx.x;
    int lane = tid & 31;
    int wid  = tid >> 5;
    int pxg0 = blockIdx.x * 128;
    int b   = pxg0 >> 12;
    int hw0 = pxg0 & 4095;

    int4*   si = (int4*)(smem + SM_SI);
    float4* sw = (float4*)(smem + SM_SW);

    // ---- sampling metadata: 9 taps x 128 px ----
    for (int e = tid; e < 1152; e += 256) {
        int n = e >> 7, h = e & 127;
        int hw = hw0 + h;
        int r = hw >> 6, c = hw & 63;
        float ox = g_offb[(size_t)(b*18 + n)*HW + hw];
        float oy = g_offb[(size_t)(b*18 + 9 + n)*HW + hw];
        float px = (float)(r + 1) + (float)(n/3 - 1) + ox;
        float py = (float)(c + 1) + (float)(n%3 - 1) + oy;
        float fx = floorf(px), fy = floorf(py);
        float qx0 = fminf(fmaxf(fx,       0.f), 65.f);
        float qx1 = fminf(fmaxf(fx + 1.f, 0.f), 65.f);
        float qy0 = fminf(fmaxf(fy,       0.f), 65.f);
        float qy1 = fminf(fmaxf(fy + 1.f, 0.f), 65.f);
        float pxc = fminf(fmaxf(px, 0.f), 65.f);
        float pyc = fminf(fmaxf(py, 0.f), 65.f);
        float glt = (1.f + (qx0 - pxc)) * (1.f + (qy0 - pyc));
        float grb = (1.f - (qx1 - pxc)) * (1.f - (qy1 - pyc));
        float glb = (1.f + (qx0 - pxc)) * (1.f - (qy1 - pyc));
        float grt = (1.f - (qx1 - pxc)) * (1.f + (qy0 - pyc));
        float mod = g_mb[(size_t)(b*9 + n)*HW + hw];
        int ix0 = (int)qx0, ix1 = (int)qx1, iy0 = (int)qy0, iy1 = (int)qy1;
#define ENC(qx,qy) (((qx)>=1 && (qx)<=64 && (qy)>=1 && (qy)<=64) ? (((qx)-1)*64 + ((qy)-1)) : -1)
        si[e] = make_int4(ENC(ix0,iy0), ENC(ix1,iy1), ENC(ix0,iy1), ENC(ix1,iy0));
#undef ENC
        sw[e] = make_float4(glt*mod, grb*mod, glb*mod, grt*mod);
    }
    __syncthreads();

    int pxB  = tid & 127;        // build role: pixel
    int half = tid >> 7;         // build role: ic half (32 ics)
    int ocb  = (wid >> 2) * 64;  // compute role
    int pxb  = (wid & 3) * 32;

    // ldmatrix per-thread row/k components
    int lrow = lane & 15;
    int lkh  = (lane >> 4) * 16;  // byte offset of k-half within row

    // ---- build chunk 0 into buf 0 ----
    {
        float4* dstA = (float4*)(smem + SM_TILE);
        const float4* srcA = (const float4*)((const unsigned char*)g_wA);
#pragma unroll
        for (int i = 0; i < 8; i++) dstA[tid + i*256] = srcA[tid + i*256];
        int4   id = si[pxB];          // tap 0
        float4 wc = sw[pxB];
        const float* img = g_h + ((size_t)(b*CH + half*32))*HW;
        unsigned char* bhi = smem + SM_TILE + 32768;
        unsigned char* blo = bhi + 16384;
#pragma unroll
        for (int ip = 0; ip < 16; ip++) {
            float v0 = dsample(img, id, wc); img += HW;
            float v1 = dsample(img, id, wc); img += HW;
            __nv_bfloat16 h0 = __float2bfloat16(v0);
            __nv_bfloat16 h1 = __float2bfloat16(v1);
            __nv_bfloat16 l0 = __float2bfloat16(v0 - __bfloat162float(h0));
            __nv_bfloat16 l1 = __float2bfloat16(v1 - __bfloat162float(h1));
            uint32_t off = SW128((uint32_t)(pxB*128 + (half*32 + ip*2)*2));
            *(uint32_t*)(bhi + off) =
                ((uint32_t)__bfloat16_as_ushort(h1) << 16) | __bfloat16_as_ushort(h0);
            *(uint32_t*)(blo + off) =
                ((uint32_t)__bfloat16_as_ushort(l1) << 16) | __bfloat16_as_ushort(l0);
        }
    }
    __syncthreads();

    float acc[4][4][4];
#pragma unroll
    for (int mt = 0; mt < 4; mt++)
#pragma unroll
        for (int nt = 0; nt < 4; nt++)
#pragma unroll
            for (int q = 0; q < 4; q++) acc[mt][nt][q] = 0.f;

    for (int c = 0; c < 18; c++) {
        int p = c & 1;
        uint32_t tb = sb + SM_TILE + p*65536;

        // ---- compute chunk c ----
#pragma unroll
        for (int ks = 0; ks < 4; ks++) {
            int kb = ks*32 + lkh;   // byte offset of this thread's k within row
            uint32_t ah[4][4], al[4][4], bb[2][4];
#pragma unroll
            for (int mt = 0; mt < 4; mt++)
                ldmx4(ah[mt], tb + SW128((uint32_t)((ocb + mt*16 + lrow)*128 + kb)));
#pragma unroll
            for (int ntp = 0; ntp < 2; ntp++)
                ldmx4(bb[ntp], tb + 32768 + SW128((uint32_t)((pxb + ntp*16 + lrow)*128 + kb)));
#pragma unroll
            for (int mt = 0; mt < 4; mt++)
#pragma unroll
                for (int nt = 0; nt < 4; nt++)
                    mma_bf16(acc[mt][nt], ah[mt], bb[nt>>1][nt&1], bb[nt>>1][(nt&1)+2]);
#pragma unroll
            for (int mt = 0; mt < 4; mt++)
                ldmx4(al[mt], tb + 16384 + SW128((uint32_t)((ocb + mt*16 + lrow)*128 + kb)));
#pragma unroll
            for (int mt = 0; mt < 4; mt++)
#pragma unroll
                for (int nt = 0; nt < 4; nt++)
                    mma_bf16(acc[mt][nt], al[mt], bb[nt>>1][nt&1], bb[nt>>1][(nt&1)+2]);
#pragma unroll
            for (int ntp = 0; ntp < 2; ntp++)
                ldmx4(bb[ntp], tb + 49152 + SW128((uint32_t)((pxb + ntp*16 + lrow)*128 + kb)));
#pragma unroll
            for (int mt = 0; mt < 4; mt++)
#pragma unroll
                for (int nt = 0; nt < 4; nt++)
                    mma_bf16(acc[mt][nt], ah[mt], bb[nt>>1][nt&1], bb[nt>>1][(nt&1)+2]);
        }

        // ---- build chunk c+1 into other buffer ----
        if (c < 17) {
            int cn = c + 1;
            unsigned char* nb = smem + SM_TILE + (1-p)*65536;
            float4* dstA = (float4*)nb;
            const float4* srcA = (const float4*)((const unsigned char*)g_wA + (size_t)cn*32768);
#pragma unroll
            for (int i = 0; i < 8; i++) dstA[tid + i*256] = srcA[tid + i*256];
            int tap = cn >> 1, ichalf = cn & 1;
            int m = tap*128 + pxB;
            int4   id = si[m];
            float4 wc = sw[m];
            const float* img = g_h + ((size_t)(b*CH + ichalf*64 + half*32))*HW;
            unsigned char* bhi = nb + 32768;
            unsigned char* blo = bhi + 16384;
#pragma unroll
            for (int ip = 0; ip < 16; ip++) {
                float v0 = dsample(img, id, wc); img += HW;
                float v1 = dsample(img, id, wc); img += HW;
                __nv_bfloat16 h0 = __float2bfloat16(v0);
                __nv_bfloat16 h1 = __float2bfloat16(v1);
                __nv_bfloat16 l0 = __float2bfloat16(v0 - __bfloat162float(h0));
                __nv_bfloat16 l1 = __float2bfloat16(v1 - __bfloat162float(h1));
                uint32_t off = SW128((uint32_t)(pxB*128 + (half*32 + ip*2)*2));
                *(uint32_t*)(bhi + off) =
                    ((uint32_t)__bfloat16_as_ushort(h1) << 16) | __bfloat16_as_ushort(h0);
                *(uint32_t*)(blo + off) =
                    ((uint32_t)__bfloat16_as_ushort(l1) << 16) | __bfloat16_as_ushort(l0);
            }
        }
        __syncthreads();
    }

    // ---- epilogue: per-warp fragment stores (float2) ----
    int g  = lane >> 2;
    int cx = (lane & 3) * 2;
#pragma unroll
    for (int mt = 0; mt < 4; mt++) {
#pragma unroll
        for (int nt = 0; nt < 4; nt++) {
            int oc = ocb + mt*16 + g;
            int px = pxb + nt*8 + cx;
            float* d0 = g_d + ((size_t)(b*CH + oc))*HW + hw0 + px;
            float* d1 = g_d + ((size_t)(b*CH + oc + 8))*HW + hw0 + px;
            *(float2*)d0 = make_float2(acc[mt][nt][0], acc[mt][nt][1]);
            *(float2*)d1 = make_float2(acc[mt][nt][2], acc[mt][nt][3]);
        }
    }
}

// ---------------- stats: per-channel mean / rstd over (B,H,W) --------------
__global__ __launch_bounds__(256) void k_stats(const float* __restrict__ src,
                                               float* __restrict__ dst) {
    __shared__ float ss[256], sq[256];
    int ch = blockIdx.x, tid = threadIdx.x;
    float s = 0.f, s2 = 0.f;
    for (int i = tid; i < BB*HW; i += 256) {
        int b = i >> 12, hw = i & 4095;
        float v = src[(size_t)(b*CH + ch)*HW + hw];
        s += v; s2 += v*v;
    }
    ss[tid] = s; sq[tid] = s2;
    __syncthreads();
    for (int o = 128; o > 0; o >>= 1) {
        if (tid < o) { ss[tid] += ss[tid+o]; sq[tid] += sq[tid+o]; }
        __syncthreads();
    }
    if (tid == 0) {
        float mean = ss[0] * (1.f/32768.f);
        float var  = sq[0] * (1.f/32768.f) - mean*mean;
        dst[ch]      = mean;
        dst[CH + ch] = rsqrtf(var + 1e-5f);
    }
}

// ---------------- K7a: bn1 + exact gelu ------------------------------------
__global__ __launch_bounds__(256) void k_bn1gelu(const float* __restrict__ g,
                                                 const float* __restrict__ bv) {
    int i = blockIdx.x * 256 + threadIdx.x;
    if (i >= BB*CH*HW) return;
    int ch = (i >> 12) & (CH-1);
    float xn = (g_d[i] - g_s1[ch]) * g_s1[CH+ch] * g[ch] + bv[ch];
    g_t[i] = 0.5f * xn * (1.f + erff(xn * 0.70710678118654752f));
}

// ---------------- K7b: depthwise2 3x3 + bias --------------------------------
__global__ __launch_bounds__(256) void k_dw2(const float* __restrict__ w,
                                             const float* __restrict__ bias) {
    int i = blockIdx.x * 256 + threadIdx.x;
    if (i >= BB*CH*HW) return;
    int hw = i & (HW-1);
    int ch = (i >> 12) & (CH-1);
    int b  = i >> 19;
    int r = hw >> 6, c = hw & 63;
    const float* img = g_t + (size_t)(b*CH + ch)*HW;
    const float* wc  = w + ch*9;
    float acc = bias[ch];
#pragma unroll
    for (int dy = -1; dy <= 1; dy++)
#pragma unroll
        for (int dx = -1; dx <= 1; dx++) {
            int rr = r + dy, cc = c + dx;
            if ((unsigned)rr < 64u && (unsigned)cc < 64u)
                acc += wc[(dy+1)*3 + (dx+1)] * img[rr*64 + cc];
        }
    g_u[i] = acc;
}

// ---------------- K9: bn2 + relu -> out -------------------------------------
__global__ __launch_bounds__(256) void k_bn2relu(const float* __restrict__ g,
                                                 const float* __restrict__ bv,
                                                 float* __restrict__ out) {
    int i = blockIdx.x * 256 + threadIdx.x;
    if (i >= BB*CH*HW) return;
    int ch = (i >> 12) & (CH-1);
    float xn = (g_u[i] - g_s2[ch]) * g_s2[CH+ch] * g[ch] + bv[ch];
    out[i] = fmaxf(xn, 0.f);
}

// ---------------- launch ----------------------------------------------------
extern "C" void kernel_launch(void* const* d_in, const int* in_sizes, int n_in,
                              void* d_out, int out_size) {
    const float* x1      = (const float*)d_in[0];
    const float* x2      = (const float*)d_in[1];
    const float* dw1_w   = (const float*)d_in[2];
    const float* dw1_b   = (const float*)d_in[3];
    const float* pw_w    = (const float*)d_in[4];
    const float* pw_b    = (const float*)d_in[5];
    const float* p_w     = (const float*)d_in[6];
    const float* p_b     = (const float*)d_in[7];
    const float* m_w     = (const float*)d_in[8];
    const float* m_b     = (const float*)d_in[9];
    const float* dcn_w   = (const float*)d_in[10];
    const float* bn1_g   = (const float*)d_in[11];
    const float* bn1_b   = (const float*)d_in[12];
    const float* dw2_w   = (const float*)d_in[13];
    const float* dw2_b   = (const float*)d_in[14];
    const float* bn2_g   = (const float*)d_in[15];
    const float* bn2_b   = (const float*)d_in[16];
    float* out = (float*)d_out;

    float *s1p, *s2p, *dp, *up;
    cudaGetSymbolAddress((void**)&s1p, g_s1);
    cudaGetSymbolAddress((void**)&s2p, g_s2);
    cudaGetSymbolAddress((void**)&dp,  g_d);
    cudaGetSymbolAddress((void**)&up,  g_u);

    cudaFuncSetAttribute(k_dgemm_tc, cudaFuncAttributeMaxDynamicSharedMemorySize, SMEM_DG);

    int prep_items = 18*16384 + CC*CH + KBIG*32;
    k_prep <<<(prep_items + 255)/256, 256>>>(dcn_w, pw_w, p_w, m_w);
    k_upcat<<<(BB*CC*HW + 255)/256, 256>>>(x1, x2);
    k_dw1  <<<(BB*CC*HW + 255)/256, 256>>>(dw1_w, dw1_b);
    k_pw   <<<PP/128, 256>>>(pw_b);
    k_offmask<<<PP/128, 256>>>(p_b, m_b);
    k_dgemm_tc<<<PP/128, 256, SMEM_DG>>>();
    k_stats<<<CH, 256>>>(dp, s1p);
    k_bn1gelu<<<(BB*CH*HW + 255)/256, 256>>>(bn1_g, bn1_b);
    k_dw2  <<<(BB*CH*HW + 255)/256, 256>>>(dw2_w, dw2_b);
    k_stats<<<CH, 256>>>(up, s2p);
    k_bn2relu<<<(BB*CH*HW + 255)/256, 256>>>(bn2_g, bn2_b, out);
}

// round 6
// speedup vs baseline: 2.7414x; 1.2831x over previous
#include <cuda_runtime.h>
#include <cuda_bf16.h>
#include <math.h>
#include <cstdint>

#define BB 8
#define CH 128
#define CC 256
#define HW 4096
#define PP 32768      // BB*HW
#define KBIG 1152     // 128 ic * 9 taps

// ---------------- scratch (static device globals; no runtime alloc) --------
static __device__ float  g_h1 [BB*CC*HW];     // fused upcat+depthwise1 out
static __device__ float  g_h  [BB*CH*HW];     // pointwise out
static __device__ float  g_offb[BB*18*HW];    // offsets
static __device__ float  g_mb [BB*9*HW];      // modulation (sigmoid)
static __device__ float  g_d  [BB*CH*HW];     // deform conv out
static __device__ float  g_t  [BB*CH*HW];     // gelu(bn1) out
static __device__ float  g_u  [BB*CH*HW];     // depthwise2 out
static __device__ float  g_s1 [2*CH];         // bn1 mean / rstd
static __device__ float  g_s2 [2*CH];         // bn2 mean / rstd
// dcn weights: per chunk c (tap=c>>1, ichalf=c&1): hi tile (8192 bf16) + lo,
// each pre-swizzled SW128 K-major 128oc x 64k
static __device__ __nv_bfloat16 g_wA [18*16384];
// pointwise weights: 4 chunks (k=64): hi 8192 + lo 8192
static __device__ __nv_bfloat16 g_pwA[4*16384];
// offset+mask weights (oc padded to 32): 18 chunks: hi 2048 + lo 2048
static __device__ __nv_bfloat16 g_omA[18*4096];

#define SW128(o)   ((o) ^ (((o) >> 3) & 0x70))

__device__ __forceinline__ uint32_t smem_u32(const void* p) {
    uint32_t a;
    asm("{ .reg .u64 t; cvta.to.shared.u64 t, %1; cvt.u32.u64 %0, t; }"
        : "=r"(a) : "l"(p));
    return a;
}
__device__ __forceinline__ void ldmx4(uint32_t* r, uint32_t addr) {
    asm volatile("ldmatrix.sync.aligned.m8n8.x4.shared.b16 {%0,%1,%2,%3}, [%4];"
                 : "=r"(r[0]), "=r"(r[1]), "=r"(r[2]), "=r"(r[3]) : "r"(addr));
}
__device__ __forceinline__ void mma_bf16(float* d, const uint32_t* a,
                                         uint32_t b0, uint32_t b1) {
    asm volatile("mma.sync.aligned.m16n8k16.row.col.f32.bf16.bf16.f32 "
                 "{%0,%1,%2,%3}, {%4,%5,%6,%7}, {%8,%9}, {%0,%1,%2,%3};"
                 : "+f"(d[0]), "+f"(d[1]), "+f"(d[2]), "+f"(d[3])
                 : "r"(a[0]), "r"(a[1]), "r"(a[2]), "r"(a[3]), "r"(b0), "r"(b1));
}
__device__ __forceinline__ void split_store(unsigned char* hi, unsigned char* lo,
                                            uint32_t off, float v0, float v1) {
    __nv_bfloat16 h0 = __float2bfloat16(v0);
    __nv_bfloat16 h1 = __float2bfloat16(v1);
    __nv_bfloat16 l0 = __float2bfloat16(v0 - __bfloat162float(h0));
    __nv_bfloat16 l1 = __float2bfloat16(v1 - __bfloat162float(h1));
    *(uint32_t*)(hi + off) = ((uint32_t)__bfloat16_as_ushort(h1) << 16) | __bfloat16_as_ushort(h0);
    *(uint32_t*)(lo + off) = ((uint32_t)__bfloat16_as_ushort(l1) << 16) | __bfloat16_as_ushort(l0);
}

// ---------------- K0: weight prep (hi/lo split + SW128 images) --------------
__global__ __launch_bounds__(256) void k_prep(const float* __restrict__ dcn_w,
                                              const float* __restrict__ pw_w,
                                              const float* __restrict__ p_w,
                                              const float* __restrict__ m_w) {
    int i = blockIdx.x * 256 + threadIdx.x;
    if (i < 18*16384) {
        int c = i >> 14, r = i & 16383;
        int s = r >> 13, e = r & 8191;
        int oc = e >> 6, ic = e & 63;
        int tap = c >> 1, ichalf = c & 1;
        float val = dcn_w[oc*KBIG + (ichalf*64 + ic)*9 + tap];
        __nv_bfloat16 hi = __float2bfloat16(val);
        __nv_bfloat16 out = s ? __float2bfloat16(val - __bfloat162float(hi)) : hi;
        g_wA[(size_t)c*16384 + s*8192 + (SW128((uint32_t)(oc*128 + ic*2)) >> 1)] = out;
        return;
    }
    i -= 18*16384;
    if (i < 4*16384) {
        int c = i >> 14, r = i & 16383;
        int s = r >> 13, e = r & 8191;
        int oc = e >> 6, ic = e & 63;
        float val = pw_w[oc*CC + c*64 + ic];
        __nv_bfloat16 hi = __float2bfloat16(val);
        __nv_bfloat16 out = s ? __float2bfloat16(val - __bfloat162float(hi)) : hi;
        g_pwA[(size_t)c*16384 + s*8192 + (SW128((uint32_t)(oc*128 + ic*2)) >> 1)] = out;
        return;
    }
    i -= 4*16384;
    if (i < 18*4096) {
        int c = i >> 12, r = i & 4095;
        int s = r >> 11, e = r & 2047;
        int oc = e >> 6, ic = e & 63;
        int tap = c >> 1, ichalf = c & 1;
        int icg = ichalf*64 + ic;
        float val = 0.f;
        if (oc < 18)      val = p_w[oc*KBIG + icg*9 + tap];
        else if (oc < 27) val = m_w[(oc-18)*KBIG + icg*9 + tap];
        __nv_bfloat16 hi = __float2bfloat16(val);
        __nv_bfloat16 out = s ? __float2bfloat16(val - __bfloat162float(hi)) : hi;
        g_omA[(size_t)c*4096 + s*2048 + (SW128((uint32_t)(oc*128 + ic*2)) >> 1)] = out;
    }
}

// ---------------- K1: fused bilinear-up2x + concat + depthwise1 -------------
// one block per (b, ch): stage 66x66 halo tile (upsampled for ch>=128), conv.
__global__ __launch_bounds__(256) void k_updw1(const float* __restrict__ x1,
                                               const float* __restrict__ x2,
                                               const float* __restrict__ w,
                                               const float* __restrict__ bias) {
    __shared__ float T[66*68];
    __shared__ float X1[32*33];
    int tid = threadIdx.x;
    int blk = blockIdx.x;
    int b = blk >> 8, ch = blk & 255;

    if (ch < CH) {
        const float* img = x2 + (size_t)(b*CH + ch)*HW;
        for (int e = tid; e < 66*66; e += 256) {
            int r = e/66, c = e - (e/66)*66;
            int rr = r - 1, cc = c - 1;
            T[r*68 + c] = ((unsigned)rr < 64u && (unsigned)cc < 64u) ? img[rr*64 + cc] : 0.f;
        }
    } else {
        const float* img = x1 + ((size_t)(b*CH + ch - CH))*1024;
        for (int e = tid; e < 1024; e += 256)
            X1[(e >> 5)*33 + (e & 31)] = img[e];
        __syncthreads();
        for (int e = tid; e < 66*66; e += 256) {
            int r = e/66, c = e - (e/66)*66;
            int rr = r - 1, cc = c - 1;
            float v = 0.f;
            if ((unsigned)rr < 64u && (unsigned)cc < 64u) {
                float sr = (float)rr * (31.0f/63.0f);
                float sc = (float)cc * (31.0f/63.0f);
                int i0 = min((int)sr, 30);
                int j0 = min((int)sc, 30);
                float ty = sr - (float)i0;
                float tx = sc - (float)j0;
                float a00 = X1[i0*33 + j0],     a10 = X1[(i0+1)*33 + j0];
                float a01 = X1[i0*33 + j0 + 1], a11 = X1[(i0+1)*33 + j0 + 1];
                v = (a00*(1.f-ty) + a10*ty)*(1.f-tx) + (a01*(1.f-ty) + a11*ty)*tx;
            }
            T[r*68 + c] = v;
        }
    }
    __syncthreads();

    const float* wc = w + ch*9;
    float w0 = wc[0], w1 = wc[1], w2 = wc[2], w3 = wc[3], w4 = wc[4],
          w5 = wc[5], w6 = wc[6], w7 = wc[7], w8 = wc[8];
    float bb = bias[ch];
    float* dst = g_h1 + (size_t)blk*HW;
#pragma unroll
    for (int i = 0; i < 16; i++) {
        int px = i*256 + tid;
        int r = px >> 6, c = px & 63;
        const float* t0 = T + r*68 + c;
        float acc = bb
            + w0*t0[0]     + w1*t0[1]     + w2*t0[2]
            + w3*t0[68]    + w4*t0[69]    + w5*t0[70]
            + w6*t0[136]   + w7*t0[137]   + w8*t0[138];
        dst[px] = acc;
    }
}

// ---------------- K3: pointwise 256->128 via mma.sync bf16x3 ----------------
// CTA 128oc x 128px; K=256 in 4 chunks of 64; 8 warps (2oc x 4px).
#define SMEM_PW (2*65536)
__global__ __launch_bounds__(256, 1) void k_pw_tc(const float* __restrict__ bias) {
    extern __shared__ __align__(1024) unsigned char smem[];
    uint32_t sb = smem_u32(smem);
    int tid  = threadIdx.x;
    int lane = tid & 31;
    int wid  = tid >> 5;
    int pxg0 = blockIdx.x * 128;
    int b   = pxg0 >> 12;
    int hw0 = pxg0 & 4095;

    int pxB  = tid & 127;
    int half = tid >> 7;
    int ocb  = (wid >> 2) * 64;
    int pxb  = (wid & 3) * 32;
    int lrow = lane & 15;
    int lkh  = (lane >> 4) * 16;

    // build chunk 0
    {
        float4* dstA = (float4*)smem;
        const float4* srcA = (const float4*)((const unsigned char*)g_pwA);
#pragma unroll
        for (int i = 0; i < 8; i++) dstA[tid + i*256] = srcA[tid + i*256];
        const float* img = g_h1 + ((size_t)(b*CC + half*32))*HW + hw0 + pxB;
        unsigned char* bhi = smem + 32768;
        unsigned char* blo = bhi + 16384;
#pragma unroll
        for (int ip = 0; ip < 16; ip++) {
            float v0 = img[0]; img += HW;
            float v1 = img[0]; img += HW;
            split_store(bhi, blo, SW128((uint32_t)(pxB*128 + (half*32 + ip*2)*2)), v0, v1);
        }
    }
    __syncthreads();

    float acc[4][4][4];
#pragma unroll
    for (int mt = 0; mt < 4; mt++)
#pragma unroll
        for (int nt = 0; nt < 4; nt++)
#pragma unroll
            for (int q = 0; q < 4; q++) acc[mt][nt][q] = 0.f;

    for (int c = 0; c < 4; c++) {
        int p = c & 1;
        uint32_t tb = sb + p*65536;
#pragma unroll
        for (int ks = 0; ks < 4; ks++) {
            int kb = ks*32 + lkh;
            uint32_t ah[4][4], al[4][4], bb[2][4];
#pragma unroll
            for (int mt = 0; mt < 4; mt++)
                ldmx4(ah[mt], tb + SW128((uint32_t)((ocb + mt*16 + lrow)*128 + kb)));
#pragma unroll
            for (int ntp = 0; ntp < 2; ntp++)
                ldmx4(bb[ntp], tb + 32768 + SW128((uint32_t)((pxb + ntp*16 + lrow)*128 + kb)));
#pragma unroll
            for (int mt = 0; mt < 4; mt++)
#pragma unroll
                for (int nt = 0; nt < 4; nt++)
                    mma_bf16(acc[mt][nt], ah[mt], bb[nt>>1][nt&1], bb[nt>>1][(nt&1)+2]);
#pragma unroll
            for (int mt = 0; mt < 4; mt++)
                ldmx4(al[mt], tb + 16384 + SW128((uint32_t)((ocb + mt*16 + lrow)*128 + kb)));
#pragma unroll
            for (int mt = 0; mt < 4; mt++)
#pragma unroll
                for (int nt = 0; nt < 4; nt++)
                    mma_bf16(acc[mt][nt], al[mt], bb[nt>>1][nt&1], bb[nt>>1][(nt&1)+2]);
#pragma unroll
            for (int ntp = 0; ntp < 2; ntp++)
                ldmx4(bb[ntp], tb + 49152 + SW128((uint32_t)((pxb + ntp*16 + lrow)*128 + kb)));
#pragma unroll
            for (int mt = 0; mt < 4; mt++)
#pragma unroll
                for (int nt = 0; nt < 4; nt++)
                    mma_bf16(acc[mt][nt], ah[mt], bb[nt>>1][nt&1], bb[nt>>1][(nt&1)+2]);
        }
        if (c < 3) {
            int cn = c + 1;
            unsigned char* nb = smem + (1-p)*65536;
            float4* dstA = (float4*)nb;
            const float4* srcA = (const float4*)((const unsigned char*)g_pwA + (size_t)cn*32768);
#pragma unroll
            for (int i = 0; i < 8; i++) dstA[tid + i*256] = srcA[tid + i*256];
            const float* img = g_h1 + ((size_t)(b*CC + cn*64 + half*32))*HW + hw0 + pxB;
            unsigned char* bhi = nb + 32768;
            unsigned char* blo = bhi + 16384;
#pragma unroll
            for (int ip = 0; ip < 16; ip++) {
                float v0 = img[0]; img += HW;
                float v1 = img[0]; img += HW;
                split_store(bhi, blo, SW128((uint32_t)(pxB*128 + (half*32 + ip*2)*2)), v0, v1);
            }
        }
        __syncthreads();
    }

    int g  = lane >> 2;
    int cx = (lane & 3) * 2;
#pragma unroll
    for (int mt = 0; mt < 4; mt++) {
#pragma unroll
        for (int nt = 0; nt < 4; nt++) {
            int oc = ocb + mt*16 + g;
            int px = pxb + nt*8 + cx;
            float b0 = bias[oc], b1 = bias[oc + 8];
            float* d0 = g_h + ((size_t)(b*CH + oc))*HW + hw0 + px;
            float* d1 = g_h + ((size_t)(b*CH + oc + 8))*HW + hw0 + px;
            *(float2*)d0 = make_float2(acc[mt][nt][0] + b0, acc[mt][nt][1] + b0);
            *(float2*)d1 = make_float2(acc[mt][nt][2] + b1, acc[mt][nt][3] + b1);
        }
    }
}

// ---------------- K4: offset+mask conv via mma.sync bf16x3 ------------------
// CTA 32oc(pad) x 128px; K=1152 in 18 chunks; 8 warps x 16px.
#define SM_NOFF  0
#define SM_OMT   5120
#define SMEM_OM  (SM_OMT + 2*40960)
__global__ __launch_bounds__(256, 1) void k_offmask_tc(const float* __restrict__ pb,
                                                       const float* __restrict__ mb) {
    extern __shared__ __align__(1024) unsigned char smem[];
    uint32_t sb = smem_u32(smem);
    int* noff = (int*)(smem + SM_NOFF);
    int tid  = threadIdx.x;
    int lane = tid & 31;
    int wid  = tid >> 5;
    int pxg0 = blockIdx.x * 128;
    int b   = pxg0 >> 12;
    int hw0 = pxg0 & 4095;

    int pxB  = tid & 127;
    int half = tid >> 7;
    int pxw  = wid * 16;
    int lrow = lane & 15;
    int lkh  = (lane >> 4) * 16;

    for (int e = tid; e < 1152; e += 256) {
        int t = e >> 7, h = e & 127;
        int hw = hw0 + h;
        int r = hw >> 6, c = hw & 63;
        int dy = t/3 - 1, dx = t%3 - 1;
        int rr = r + dy, cc = c + dx;
        noff[e] = ((unsigned)rr < 64u && (unsigned)cc < 64u) ? (rr*64 + cc) : -1;
    }
    __syncthreads();

    // build chunk 0
    {
        unsigned char* nb = smem + SM_OMT;
        float4* dstA = (float4*)nb;
        const float4* srcA = (const float4*)((const unsigned char*)g_omA);
#pragma unroll
        for (int i = 0; i < 2; i++) dstA[tid + i*256] = srcA[tid + i*256];
        int idx = noff[pxB];   // tap 0
        const float* img = g_h + ((size_t)(b*CH + half*32))*HW;
        unsigned char* bhi = nb + 8192;
        unsigned char* blo = nb + 24576;
#pragma unroll
        for (int ip = 0; ip < 16; ip++) {
            float v0 = (idx >= 0) ? img[idx] : 0.f; img += HW;
            float v1 = (idx >= 0) ? img[idx] : 0.f; img += HW;
            split_store(bhi, blo, SW128((uint32_t)(pxB*128 + (half*32 + ip*2)*2)), v0, v1);
        }
    }
    __syncthreads();

    float acc[2][2][4];
#pragma unroll
    for (int mt = 0; mt < 2; mt++)
#pragma unroll
        for (int nt = 0; nt < 2; nt++)
#pragma unroll
            for (int q = 0; q < 4; q++) acc[mt][nt][q] = 0.f;

    for (int c = 0; c < 18; c++) {
        int p = c & 1;
        uint32_t tb = sb + SM_OMT + p*40960;
#pragma unroll
        for (int ks = 0; ks < 4; ks++) {
            int kb = ks*32 + lkh;
            uint32_t ah[2][4], al[2][4], bh[4], bl[4];
#pragma unroll
            for (int mt = 0; mt < 2; mt++)
                ldmx4(ah[mt], tb + SW128((uint32_t)((mt*16 + lrow)*128 + kb)));
            ldmx4(bh, tb + 8192 + SW128((uint32_t)((pxw + lrow)*128 + kb)));
#pragma unroll
            for (int mt = 0; mt < 2; mt++)
#pragma unroll
                for (int nt = 0; nt < 2; nt++)
                    mma_bf16(acc[mt][nt], ah[mt], bh[nt], bh[nt+2]);
#pragma unroll
            for (int mt = 0; mt < 2; mt++)
                ldmx4(al[mt], tb + 4096 + SW128((uint32_t)((mt*16 + lrow)*128 + kb)));
#pragma unroll
            for (int mt = 0; mt < 2; mt++)
#pragma unroll
                for (int nt = 0; nt < 2; nt++)
                    mma_bf16(acc[mt][nt], al[mt], bh[nt], bh[nt+2]);
            ldmx4(bl, tb + 24576 + SW128((uint32_t)((pxw + lrow)*128 + kb)));
#pragma unroll
            for (int mt = 0; mt < 2; mt++)
#pragma unroll
                for (int nt = 0; nt < 2; nt++)
                    mma_bf16(acc[mt][nt], ah[mt], bl[nt], bl[nt+2]);
        }
        if (c < 17) {
            int cn = c + 1;
            unsigned char* nb = smem + SM_OMT + (1-p)*40960;
            float4* dstA = (float4*)nb;
            const float4* srcA = (const float4*)((const unsigned char*)g_omA + (size_t)cn*8192);
#pragma unroll
            for (int i = 0; i < 2; i++) dstA[tid + i*256] = srcA[tid + i*256];
            int tap = cn >> 1, ichalf = cn & 1;
            int idx = noff[tap*128 + pxB];
            const float* img = g_h + ((size_t)(b*CH + ichalf*64 + half*32))*HW;
            unsigned char* bhi = nb + 8192;
            unsigned char* blo = nb + 24576;
#pragma unroll
            for (int ip = 0; ip < 16; ip++) {
                float v0 = (idx >= 0) ? img[idx] : 0.f; img += HW;
                float v1 = (idx >= 0) ? img[idx] : 0.f; img += HW;
                split_store(bhi, blo, SW128((uint32_t)(pxB*128 + (half*32 + ip*2)*2)), v0, v1);
            }
        }
        __syncthreads();
    }

    int g  = lane >> 2;
    int cx = (lane & 3) * 2;
#pragma unroll
    for (int mt = 0; mt < 2; mt++) {
#pragma unroll
        for (int nt = 0; nt < 2; nt++) {
            int px = hw0 + pxw + nt*8 + cx;
#pragma unroll
            for (int h2 = 0; h2 < 2; h2++) {
                int oc = mt*16 + g + h2*8;
                float v0 = acc[mt][nt][h2*2], v1 = acc[mt][nt][h2*2 + 1];
                if (oc < 18) {
                    float bbv = pb[oc];
                    float* d = g_offb + (size_t)(b*18 + oc)*HW + px;
                    *(float2*)d = make_float2(v0 + bbv, v1 + bbv);
                } else if (oc < 27) {
                    float bbv = mb[oc - 18];
                    float* d = g_mb + (size_t)(b*9 + oc - 18)*HW + px;
                    *(float2*)d = make_float2(1.f/(1.f + expf(-(v0 + bbv))),
                                              1.f/(1.f + expf(-(v1 + bbv))));
                }
            }
        }
    }
}

// ---------------- K5: deform conv via mma.sync bf16x3 (unchanged) -----------
#define SM_SI    0
#define SM_SW    18432
#define SM_TILE  36864
#define SMEM_DG  (SM_TILE + 2*65536)

__device__ __forceinline__ float dsample(const float* img, int4 id, float4 w) {
    float v = 0.f;
    if (id.x >= 0) v += w.x * img[id.x];
    if (id.y >= 0) v += w.y * img[id.y];
    if (id.z >= 0) v += w.z * img[id.z];
    if (id.w >= 0) v += w.w * img[id.w];
    return v;
}

__global__ __launch_bounds__(256, 1) void k_dgemm_tc() {
    extern __shared__ __align__(1024) unsigned char smem[];
    uint32_t sb = smem_u32(smem);
    int tid  = threadIdx.x;
    int lane = tid & 31;
    int wid  = tid >> 5;
    int pxg0 = blockIdx.x * 128;
    int b   = pxg0 >> 12;
    int hw0 = pxg0 & 4095;

    int4*   si = (int4*)(smem + SM_SI);
    float4* sw = (float4*)(smem + SM_SW);

    for (int e = tid; e < 1152; e += 256) {
        int n = e >> 7, h = e & 127;
        int hw = hw0 + h;
        int r = hw >> 6, c = hw & 63;
        float ox = g_offb[(size_t)(b*18 + n)*HW + hw];
        float oy = g_offb[(size_t)(b*18 + 9 + n)*HW + hw];
        float px = (float)(r + 1) + (float)(n/3 - 1) + ox;
        float py = (float)(c + 1) + (float)(n%3 - 1) + oy;
        float fx = floorf(px), fy = floorf(py);
        float qx0 = fminf(fmaxf(fx,       0.f), 65.f);
        float qx1 = fminf(fmaxf(fx + 1.f, 0.f), 65.f);
        float qy0 = fminf(fmaxf(fy,       0.f), 65.f);
        float qy1 = fminf(fmaxf(fy + 1.f, 0.f), 65.f);
        float pxc = fminf(fmaxf(px, 0.f), 65.f);
        float pyc = fminf(fmaxf(py, 0.f), 65.f);
        float glt = (1.f + (qx0 - pxc)) * (1.f + (qy0 - pyc));
        float grb = (1.f - (qx1 - pxc)) * (1.f - (qy1 - pyc));
        float glb = (1.f + (qx0 - pxc)) * (1.f - (qy1 - pyc));
        float grt = (1.f - (qx1 - pxc)) * (1.f + (qy0 - pyc));
        float mod = g_mb[(size_t)(b*9 + n)*HW + hw];
        int ix0 = (int)qx0, ix1 = (int)qx1, iy0 = (int)qy0, iy1 = (int)qy1;
#define ENC(qx,qy) (((qx)>=1 && (qx)<=64 && (qy)>=1 && (qy)<=64) ? (((qx)-1)*64 + ((qy)-1)) : -1)
        si[e] = make_int4(ENC(ix0,iy0), ENC(ix1,iy1), ENC(ix0,iy1), ENC(ix1,iy0));
#undef ENC
        sw[e] = make_float4(glt*mod, grb*mod, glb*mod, grt*mod);
    }
    __syncthreads();

    int pxB  = tid & 127;
    int half = tid >> 7;
    int ocb  = (wid >> 2) * 64;
    int pxb  = (wid & 3) * 32;
    int lrow = lane & 15;
    int lkh  = (lane >> 4) * 16;

    {
        float4* dstA = (float4*)(smem + SM_TILE);
        const float4* srcA = (const float4*)((const unsigned char*)g_wA);
#pragma unroll
        for (int i = 0; i < 8; i++) dstA[tid + i*256] = srcA[tid + i*256];
        int4   id = si[pxB];
        float4 wc = sw[pxB];
        const float* img = g_h + ((size_t)(b*CH + half*32))*HW;
        unsigned char* bhi = smem + SM_TILE + 32768;
        unsigned char* blo = bhi + 16384;
#pragma unroll
        for (int ip = 0; ip < 16; ip++) {
            float v0 = dsample(img, id, wc); img += HW;
            float v1 = dsample(img, id, wc); img += HW;
            split_store(bhi, blo, SW128((uint32_t)(pxB*128 + (half*32 + ip*2)*2)), v0, v1);
        }
    }
    __syncthreads();

    float acc[4][4][4];
#pragma unroll
    for (int mt = 0; mt < 4; mt++)
#pragma unroll
        for (int nt = 0; nt < 4; nt++)
#pragma unroll
            for (int q = 0; q < 4; q++) acc[mt][nt][q] = 0.f;

    for (int c = 0; c < 18; c++) {
        int p = c & 1;
        uint32_t tb = sb + SM_TILE + p*65536;
#pragma unroll
        for (int ks = 0; ks < 4; ks++) {
            int kb = ks*32 + lkh;
            uint32_t ah[4][4], al[4][4], bb[2][4];
#pragma unroll
            for (int mt = 0; mt < 4; mt++)
                ldmx4(ah[mt], tb + SW128((uint32_t)((ocb + mt*16 + lrow)*128 + kb)));
#pragma unroll
            for (int ntp = 0; ntp < 2; ntp++)
                ldmx4(bb[ntp], tb + 32768 + SW128((uint32_t)((pxb + ntp*16 + lrow)*128 + kb)));
#pragma unroll
            for (int mt = 0; mt < 4; mt++)
#pragma unroll
                for (int nt = 0; nt < 4; nt++)
                    mma_bf16(acc[mt][nt], ah[mt], bb[nt>>1][nt&1], bb[nt>>1][(nt&1)+2]);
#pragma unroll
            for (int mt = 0; mt < 4; mt++)
                ldmx4(al[mt], tb + 16384 + SW128((uint32_t)((ocb + mt*16 + lrow)*128 + kb)));
#pragma unroll
            for (int mt = 0; mt < 4; mt++)
#pragma unroll
                for (int nt = 0; nt < 4; nt++)
                    mma_bf16(acc[mt][nt], al[mt], bb[nt>>1][nt&1], bb[nt>>1][(nt&1)+2]);
#pragma unroll
            for (int ntp = 0; ntp < 2; ntp++)
                ldmx4(bb[ntp], tb + 49152 + SW128((uint32_t)((pxb + ntp*16 + lrow)*128 + kb)));
#pragma unroll
            for (int mt = 0; mt < 4; mt++)
#pragma unroll
                for (int nt = 0; nt < 4; nt++)
                    mma_bf16(acc[mt][nt], ah[mt], bb[nt>>1][nt&1], bb[nt>>1][(nt&1)+2]);
        }
        if (c < 17) {
            int cn = c + 1;
            unsigned char* nb = smem + SM_TILE + (1-p)*65536;
            float4* dstA = (float4*)nb;
            const float4* srcA = (const float4*)((const unsigned char*)g_wA + (size_t)cn*32768);
#pragma unroll
            for (int i = 0; i < 8; i++) dstA[tid + i*256] = srcA[tid + i*256];
            int tap = cn >> 1, ichalf = cn & 1;
            int m = tap*128 + pxB;
            int4   id = si[m];
            float4 wc = sw[m];
            const float* img = g_h + ((size_t)(b*CH + ichalf*64 + half*32))*HW;
            unsigned char* bhi = nb + 32768;
            unsigned char* blo = bhi + 16384;
#pragma unroll
            for (int ip = 0; ip < 16; ip++) {
                float v0 = dsample(img, id, wc); img += HW;
                float v1 = dsample(img, id, wc); img += HW;
                split_store(bhi, blo, SW128((uint32_t)(pxB*128 + (half*32 + ip*2)*2)), v0, v1);
            }
        }
        __syncthreads();
    }

    int g  = lane >> 2;
    int cx = (lane & 3) * 2;
#pragma unroll
    for (int mt = 0; mt < 4; mt++) {
#pragma unroll
        for (int nt = 0; nt < 4; nt++) {
            int oc = ocb + mt*16 + g;
            int px = pxb + nt*8 + cx;
            float* d0 = g_d + ((size_t)(b*CH + oc))*HW + hw0 + px;
            float* d1 = g_d + ((size_t)(b*CH + oc + 8))*HW + hw0 + px;
            *(float2*)d0 = make_float2(acc[mt][nt][0], acc[mt][nt][1]);
            *(float2*)d1 = make_float2(acc[mt][nt][2], acc[mt][nt][3]);
        }
    }
}

// ---------------- stats: per-channel mean / rstd over (B,H,W) --------------
__global__ __launch_bounds__(256) void k_stats(const float* __restrict__ src,
                                               float* __restrict__ dst) {
    __shared__ float ss[256], sq[256];
    int ch = blockIdx.x, tid = threadIdx.x;
    float s = 0.f, s2 = 0.f;
    for (int i = tid; i < BB*HW; i += 256) {
        int b = i >> 12, hw = i & 4095;
        float v = src[(size_t)(b*CH + ch)*HW + hw];
        s += v; s2 += v*v;
    }
    ss[tid] = s; sq[tid] = s2;
    __syncthreads();
    for (int o = 128; o > 0; o >>= 1) {
        if (tid < o) { ss[tid] += ss[tid+o]; sq[tid] += sq[tid+o]; }
        __syncthreads();
    }
    if (tid == 0) {
        float mean = ss[0] * (1.f/32768.f);
        float var  = sq[0] * (1.f/32768.f) - mean*mean;
        dst[ch]      = mean;
        dst[CH + ch] = rsqrtf(var + 1e-5f);
    }
}

// ---------------- K7a: bn1 + exact gelu ------------------------------------
__global__ __launch_bounds__(256) void k_bn1gelu(const float* __restrict__ g,
                                                 const float* __restrict__ bv) {
    int i = blockIdx.x * 256 + threadIdx.x;
    if (i >= BB*CH*HW) return;
    int ch = (i >> 12) & (CH-1);
    float xn = (g_d[i] - g_s1[ch]) * g_s1[CH+ch] * g[ch] + bv[ch];
    g_t[i] = 0.5f * xn * (1.f + erff(xn * 0.70710678118654752f));
}

// ---------------- K7b: depthwise2 3x3 + bias --------------------------------
__global__ __launch_bounds__(256) void k_dw2(const float* __restrict__ w,
                                             const float* __restrict__ bias) {
    int i = blockIdx.x * 256 + threadIdx.x;
    if (i >= BB*CH*HW) return;
    int hw = i & (HW-1);
    int ch = (i >> 12) & (CH-1);
    int b  = i >> 19;
    int r = hw >> 6, c = hw & 63;
    const float* img = g_t + (size_t)(b*CH + ch)*HW;
    const float* wc  = w + ch*9;
    float acc = bias[ch];
#pragma unroll
    for (int dy = -1; dy <= 1; dy++)
#pragma unroll
        for (int dx = -1; dx <= 1; dx++) {
            int rr = r + dy, cc = c + dx;
            if ((unsigned)rr < 64u && (unsigned)cc < 64u)
                acc += wc[(dy+1)*3 + (dx+1)] * img[rr*64 + cc];
        }
    g_u[i] = acc;
}

// ---------------- K9: bn2 + relu -> out -------------------------------------
__global__ __launch_bounds__(256) void k_bn2relu(const float* __restrict__ g,
                                                 const float* __restrict__ bv,
                                                 float* __restrict__ out) {
    int i = blockIdx.x * 256 + threadIdx.x;
    if (i >= BB*CH*HW) return;
    int ch = (i >> 12) & (CH-1);
    float xn = (g_u[i] - g_s2[ch]) * g_s2[CH+ch] * g[ch] + bv[ch];
    out[i] = fmaxf(xn, 0.f);
}

// ---------------- launch ----------------------------------------------------
extern "C" void kernel_launch(void* const* d_in, const int* in_sizes, int n_in,
                              void* d_out, int out_size) {
    const float* x1      = (const float*)d_in[0];
    const float* x2      = (const float*)d_in[1];
    const float* dw1_w   = (const float*)d_in[2];
    const float* dw1_b   = (const float*)d_in[3];
    const float* pw_w    = (const float*)d_in[4];
    const float* pw_b    = (const float*)d_in[5];
    const float* p_w     = (const float*)d_in[6];
    const float* p_b     = (const float*)d_in[7];
    const float* m_w     = (const float*)d_in[8];
    const float* m_b     = (const float*)d_in[9];
    const float* dcn_w   = (const float*)d_in[10];
    const float* bn1_g   = (const float*)d_in[11];
    const float* bn1_b   = (const float*)d_in[12];
    const float* dw2_w   = (const float*)d_in[13];
    const float* dw2_b   = (const float*)d_in[14];
    const float* bn2_g   = (const float*)d_in[15];
    const float* bn2_b   = (const float*)d_in[16];
    float* out = (float*)d_out;

    float *s1p, *s2p, *dp, *up;
    cudaGetSymbolAddress((void**)&s1p, g_s1);
    cudaGetSymbolAddress((void**)&s2p, g_s2);
    cudaGetSymbolAddress((void**)&dp,  g_d);
    cudaGetSymbolAddress((void**)&up,  g_u);

    cudaFuncSetAttribute(k_dgemm_tc,   cudaFuncAttributeMaxDynamicSharedMemorySize, SMEM_DG);
    cudaFuncSetAttribute(k_pw_tc,      cudaFuncAttributeMaxDynamicSharedMemorySize, SMEM_PW);
    cudaFuncSetAttribute(k_offmask_tc, cudaFuncAttributeMaxDynamicSharedMemorySize, SMEM_OM);

    int prep_items = 18*16384 + 4*16384 + 18*4096;
    k_prep <<<(prep_items + 255)/256, 256>>>(dcn_w, pw_w, p_w, m_w);
    k_updw1<<<BB*CC, 256>>>(x1, x2, dw1_w, dw1_b);
    k_pw_tc<<<PP/128, 256, SMEM_PW>>>(pw_b);
    k_offmask_tc<<<PP/128, 256, SMEM_OM>>>(p_b, m_b);
    k_dgemm_tc<<<PP/128, 256, SMEM_DG>>>();
    k_stats<<<CH, 256>>>(dp, s1p);
    k_bn1gelu<<<(BB*CH*HW + 255)/256, 256>>>(bn1_g, bn1_b);
    k_dw2  <<<(BB*CH*HW + 255)/256, 256>>>(dw2_w, dw2_b);
    k_stats<<<CH, 256>>>(up, s2p);
    k_bn2relu<<<(BB*CH*HW + 255)/256, 256>>>(bn2_g, bn2_b, out);
}

// round 7
// speedup vs baseline: 3.0532x; 1.1137x over previous
#include <cuda_runtime.h>
#include <cuda_bf16.h>
#include <math.h>
#include <cstdint>

#define BB 8
#define CH 128
#define CC 256
#define HW 4096
#define PP 32768      // BB*HW
#define KBIG 1152     // 128 ic * 9 taps

// ---------------- scratch (static device globals; no runtime alloc) --------
static __device__ float  g_h1 [BB*CC*HW];     // fused upcat+depthwise1 out
static __device__ float  g_h  [BB*CH*HW];     // pointwise out
static __device__ float  g_offb[BB*18*HW];    // offsets
static __device__ float  g_mb [BB*9*HW];      // modulation (sigmoid)
static __device__ float  g_d  [BB*CH*HW];     // deform conv out
static __device__ float  g_u  [BB*CH*HW];     // depthwise2 out
static __device__ float  g_s1 [2*CH];         // bn1 mean / rstd
static __device__ float  g_s2 [2*CH];         // bn2 mean / rstd
static __device__ __nv_bfloat16 g_wA [18*16384];  // dcn w: hi+lo SW128 images
static __device__ __nv_bfloat16 g_pwA[4*16384];   // pw w: hi+lo SW128 images
static __device__ __nv_bfloat16 g_omA[18*4096];   // off+mask w: hi+lo images

#define SW128(o)   ((o) ^ (((o) >> 3) & 0x70))

__device__ __forceinline__ uint32_t smem_u32(const void* p) {
    uint32_t a;
    asm("{ .reg .u64 t; cvta.to.shared.u64 t, %1; cvt.u32.u64 %0, t; }"
        : "=r"(a) : "l"(p));
    return a;
}
__device__ __forceinline__ void ldmx4(uint32_t* r, uint32_t addr) {
    asm volatile("ldmatrix.sync.aligned.m8n8.x4.shared.b16 {%0,%1,%2,%3}, [%4];"
                 : "=r"(r[0]), "=r"(r[1]), "=r"(r[2]), "=r"(r[3]) : "r"(addr));
}
__device__ __forceinline__ void mma_bf16(float* d, const uint32_t* a,
                                         uint32_t b0, uint32_t b1) {
    asm volatile("mma.sync.aligned.m16n8k16.row.col.f32.bf16.bf16.f32 "
                 "{%0,%1,%2,%3}, {%4,%5,%6,%7}, {%8,%9}, {%0,%1,%2,%3};"
                 : "+f"(d[0]), "+f"(d[1]), "+f"(d[2]), "+f"(d[3])
                 : "r"(a[0]), "r"(a[1]), "r"(a[2]), "r"(a[3]), "r"(b0), "r"(b1));
}
__device__ __forceinline__ void split_store(unsigned char* hi, unsigned char* lo,
                                            uint32_t off, float v0, float v1) {
    __nv_bfloat16 h0 = __float2bfloat16(v0);
    __nv_bfloat16 h1 = __float2bfloat16(v1);
    __nv_bfloat16 l0 = __float2bfloat16(v0 - __bfloat162float(h0));
    __nv_bfloat16 l1 = __float2bfloat16(v1 - __bfloat162float(h1));
    *(uint32_t*)(hi + off) = ((uint32_t)__bfloat16_as_ushort(h1) << 16) | __bfloat16_as_ushort(h0);
    *(uint32_t*)(lo + off) = ((uint32_t)__bfloat16_as_ushort(l1) << 16) | __bfloat16_as_ushort(l0);
}
__device__ __forceinline__ void hi_store(unsigned char* hi, uint32_t off,
                                         float v0, float v1) {
    __nv_bfloat16 h0 = __float2bfloat16(v0);
    __nv_bfloat16 h1 = __float2bfloat16(v1);
    *(uint32_t*)(hi + off) = ((uint32_t)__bfloat16_as_ushort(h1) << 16) | __bfloat16_as_ushort(h0);
}

// ---------------- K0: weight prep (hi/lo split + SW128 images) --------------
__global__ __launch_bounds__(256) void k_prep(const float* __restrict__ dcn_w,
                                              const float* __restrict__ pw_w,
                                              const float* __restrict__ p_w,
                                              const float* __restrict__ m_w) {
    int i = blockIdx.x * 256 + threadIdx.x;
    if (i < 18*16384) {
        int c = i >> 14, r = i & 16383;
        int s = r >> 13, e = r & 8191;
        int oc = e >> 6, ic = e & 63;
        int tap = c >> 1, ichalf = c & 1;
        float val = dcn_w[oc*KBIG + (ichalf*64 + ic)*9 + tap];
        __nv_bfloat16 hi = __float2bfloat16(val);
        __nv_bfloat16 out = s ? __float2bfloat16(val - __bfloat162float(hi)) : hi;
        g_wA[(size_t)c*16384 + s*8192 + (SW128((uint32_t)(oc*128 + ic*2)) >> 1)] = out;
        return;
    }
    i -= 18*16384;
    if (i < 4*16384) {
        int c = i >> 14, r = i & 16383;
        int s = r >> 13, e = r & 8191;
        int oc = e >> 6, ic = e & 63;
        float val = pw_w[oc*CC + c*64 + ic];
        __nv_bfloat16 hi = __float2bfloat16(val);
        __nv_bfloat16 out = s ? __float2bfloat16(val - __bfloat162float(hi)) : hi;
        g_pwA[(size_t)c*16384 + s*8192 + (SW128((uint32_t)(oc*128 + ic*2)) >> 1)] = out;
        return;
    }
    i -= 4*16384;
    if (i < 18*4096) {
        int c = i >> 12, r = i & 4095;
        int s = r >> 11, e = r & 2047;
        int oc = e >> 6, ic = e & 63;
        int tap = c >> 1, ichalf = c & 1;
        int icg = ichalf*64 + ic;
        float val = 0.f;
        if (oc < 18)      val = p_w[oc*KBIG + icg*9 + tap];
        else if (oc < 27) val = m_w[(oc-18)*KBIG + icg*9 + tap];
        __nv_bfloat16 hi = __float2bfloat16(val);
        __nv_bfloat16 out = s ? __float2bfloat16(val - __bfloat162float(hi)) : hi;
        g_omA[(size_t)c*4096 + s*2048 + (SW128((uint32_t)(oc*128 + ic*2)) >> 1)] = out;
    }
}

// ---------------- K1: fused bilinear-up2x + concat + depthwise1 -------------
__global__ __launch_bounds__(256) void k_updw1(const float* __restrict__ x1,
                                               const float* __restrict__ x2,
                                               const float* __restrict__ w,
                                               const float* __restrict__ bias) {
    __shared__ float T[66*68];
    __shared__ float X1[32*33];
    int tid = threadIdx.x;
    int blk = blockIdx.x;
    int b = blk >> 8, ch = blk & 255;

    if (ch < CH) {
        const float* img = x2 + (size_t)(b*CH + ch)*HW;
        for (int e = tid; e < 66*66; e += 256) {
            int r = e/66, c = e - (e/66)*66;
            int rr = r - 1, cc = c - 1;
            T[r*68 + c] = ((unsigned)rr < 64u && (unsigned)cc < 64u) ? img[rr*64 + cc] : 0.f;
        }
    } else {
        const float* img = x1 + ((size_t)(b*CH + ch - CH))*1024;
        for (int e = tid; e < 1024; e += 256)
            X1[(e >> 5)*33 + (e & 31)] = img[e];
        __syncthreads();
        for (int e = tid; e < 66*66; e += 256) {
            int r = e/66, c = e - (e/66)*66;
            int rr = r - 1, cc = c - 1;
            float v = 0.f;
            if ((unsigned)rr < 64u && (unsigned)cc < 64u) {
                float sr = (float)rr * (31.0f/63.0f);
                float sc = (float)cc * (31.0f/63.0f);
                int i0 = min((int)sr, 30);
                int j0 = min((int)sc, 30);
                float ty = sr - (float)i0;
                float tx = sc - (float)j0;
                float a00 = X1[i0*33 + j0],     a10 = X1[(i0+1)*33 + j0];
                float a01 = X1[i0*33 + j0 + 1], a11 = X1[(i0+1)*33 + j0 + 1];
                v = (a00*(1.f-ty) + a10*ty)*(1.f-tx) + (a01*(1.f-ty) + a11*ty)*tx;
            }
            T[r*68 + c] = v;
        }
    }
    __syncthreads();

    const float* wc = w + ch*9;
    float w0 = wc[0], w1 = wc[1], w2 = wc[2], w3 = wc[3], w4 = wc[4],
          w5 = wc[5], w6 = wc[6], w7 = wc[7], w8 = wc[8];
    float bb = bias[ch];
    float* dst = g_h1 + (size_t)blk*HW;
#pragma unroll
    for (int i = 0; i < 16; i++) {
        int px = i*256 + tid;
        int r = px >> 6, c = px & 63;
        const float* t0 = T + r*68 + c;
        dst[px] = bb
            + w0*t0[0]     + w1*t0[1]     + w2*t0[2]
            + w3*t0[68]    + w4*t0[69]    + w5*t0[70]
            + w6*t0[136]   + w7*t0[137]   + w8*t0[138];
    }
}

// ---------------- K3: pointwise 256->128 via mma.sync bf16x3 ----------------
#define SMEM_PW (2*65536)
__global__ __launch_bounds__(256, 1) void k_pw_tc(const float* __restrict__ bias) {
    extern __shared__ __align__(1024) unsigned char smem[];
    uint32_t sb = smem_u32(smem);
    int tid  = threadIdx.x;
    int lane = tid & 31;
    int wid  = tid >> 5;
    int pxg0 = blockIdx.x * 128;
    int b   = pxg0 >> 12;
    int hw0 = pxg0 & 4095;

    int pxB  = tid & 127;
    int half = tid >> 7;
    int ocb  = (wid >> 2) * 64;
    int pxb  = (wid & 3) * 32;
    int lrow = lane & 15;
    int lkh  = (lane >> 4) * 16;

    {
        float4* dstA = (float4*)smem;
        const float4* srcA = (const float4*)((const unsigned char*)g_pwA);
#pragma unroll
        for (int i = 0; i < 8; i++) dstA[tid + i*256] = srcA[tid + i*256];
        const float* img = g_h1 + ((size_t)(b*CC + half*32))*HW + hw0 + pxB;
        unsigned char* bhi = smem + 32768;
        unsigned char* blo = bhi + 16384;
#pragma unroll
        for (int ip = 0; ip < 16; ip++) {
            float v0 = img[0]; img += HW;
            float v1 = img[0]; img += HW;
            split_store(bhi, blo, SW128((uint32_t)(pxB*128 + (half*32 + ip*2)*2)), v0, v1);
        }
    }
    __syncthreads();

    float acc[4][4][4];
#pragma unroll
    for (int mt = 0; mt < 4; mt++)
#pragma unroll
        for (int nt = 0; nt < 4; nt++)
#pragma unroll
            for (int q = 0; q < 4; q++) acc[mt][nt][q] = 0.f;

    for (int c = 0; c < 4; c++) {
        int p = c & 1;
        uint32_t tb = sb + p*65536;
#pragma unroll
        for (int ks = 0; ks < 4; ks++) {
            int kb = ks*32 + lkh;
            uint32_t ah[4][4], al[4][4], bb[2][4];
#pragma unroll
            for (int mt = 0; mt < 4; mt++)
                ldmx4(ah[mt], tb + SW128((uint32_t)((ocb + mt*16 + lrow)*128 + kb)));
#pragma unroll
            for (int ntp = 0; ntp < 2; ntp++)
                ldmx4(bb[ntp], tb + 32768 + SW128((uint32_t)((pxb + ntp*16 + lrow)*128 + kb)));
#pragma unroll
            for (int mt = 0; mt < 4; mt++)
#pragma unroll
                for (int nt = 0; nt < 4; nt++)
                    mma_bf16(acc[mt][nt], ah[mt], bb[nt>>1][nt&1], bb[nt>>1][(nt&1)+2]);
#pragma unroll
            for (int mt = 0; mt < 4; mt++)
                ldmx4(al[mt], tb + 16384 + SW128((uint32_t)((ocb + mt*16 + lrow)*128 + kb)));
#pragma unroll
            for (int mt = 0; mt < 4; mt++)
#pragma unroll
                for (int nt = 0; nt < 4; nt++)
                    mma_bf16(acc[mt][nt], al[mt], bb[nt>>1][nt&1], bb[nt>>1][(nt&1)+2]);
#pragma unroll
            for (int ntp = 0; ntp < 2; ntp++)
                ldmx4(bb[ntp], tb + 49152 + SW128((uint32_t)((pxb + ntp*16 + lrow)*128 + kb)));
#pragma unroll
            for (int mt = 0; mt < 4; mt++)
#pragma unroll
                for (int nt = 0; nt < 4; nt++)
                    mma_bf16(acc[mt][nt], ah[mt], bb[nt>>1][nt&1], bb[nt>>1][(nt&1)+2]);
        }
        if (c < 3) {
            int cn = c + 1;
            unsigned char* nb = smem + (1-p)*65536;
            float4* dstA = (float4*)nb;
            const float4* srcA = (const float4*)((const unsigned char*)g_pwA + (size_t)cn*32768);
#pragma unroll
            for (int i = 0; i < 8; i++) dstA[tid + i*256] = srcA[tid + i*256];
            const float* img = g_h1 + ((size_t)(b*CC + cn*64 + half*32))*HW + hw0 + pxB;
            unsigned char* bhi = nb + 32768;
            unsigned char* blo = bhi + 16384;
#pragma unroll
            for (int ip = 0; ip < 16; ip++) {
                float v0 = img[0]; img += HW;
                float v1 = img[0]; img += HW;
                split_store(bhi, blo, SW128((uint32_t)(pxB*128 + (half*32 + ip*2)*2)), v0, v1);
            }
        }
        __syncthreads();
    }

    int g  = lane >> 2;
    int cx = (lane & 3) * 2;
#pragma unroll
    for (int mt = 0; mt < 4; mt++) {
#pragma unroll
        for (int nt = 0; nt < 4; nt++) {
            int oc = ocb + mt*16 + g;
            int px = pxb + nt*8 + cx;
            float b0 = bias[oc], b1 = bias[oc + 8];
            float* d0 = g_h + ((size_t)(b*CH + oc))*HW + hw0 + px;
            float* d1 = g_h + ((size_t)(b*CH + oc + 8))*HW + hw0 + px;
            *(float2*)d0 = make_float2(acc[mt][nt][0] + b0, acc[mt][nt][1] + b0);
            *(float2*)d1 = make_float2(acc[mt][nt][2] + b1, acc[mt][nt][3] + b1);
        }
    }
}

// ---------------- K4: offset+mask conv via mma.sync (A hi+lo, B hi only) ----
// CTA 32oc(pad) x 128px; K=1152 in 18 chunks; smem 54KB -> 2 CTAs/SM.
#define SM_NOFF  0
#define SM_OMT   5120
#define OM_BUF   24576   // Ahi 4096 | Alo 4096 | Bhi 16384
#define SMEM_OM  (SM_OMT + 2*OM_BUF)
__global__ __launch_bounds__(256, 2) void k_offmask_tc(const float* __restrict__ pb,
                                                       const float* __restrict__ mb) {
    extern __shared__ __align__(1024) unsigned char smem[];
    uint32_t sb = smem_u32(smem);
    int* noff = (int*)(smem + SM_NOFF);
    int tid  = threadIdx.x;
    int lane = tid & 31;
    int wid  = tid >> 5;
    int pxg0 = blockIdx.x * 128;
    int b   = pxg0 >> 12;
    int hw0 = pxg0 & 4095;

    int pxB  = tid & 127;
    int half = tid >> 7;
    int pxw  = wid * 16;
    int lrow = lane & 15;
    int lkh  = (lane >> 4) * 16;

    for (int e = tid; e < 1152; e += 256) {
        int t = e >> 7, h = e & 127;
        int hw = hw0 + h;
        int r = hw >> 6, c = hw & 63;
        int dy = t/3 - 1, dx = t%3 - 1;
        int rr = r + dy, cc = c + dx;
        noff[e] = ((unsigned)rr < 64u && (unsigned)cc < 64u) ? (rr*64 + cc) : -1;
    }
    __syncthreads();

    // build chunk 0
    {
        unsigned char* nb = smem + SM_OMT;
        float4* dstA = (float4*)nb;
        const float4* srcA = (const float4*)((const unsigned char*)g_omA);
#pragma unroll
        for (int i = 0; i < 2; i++) dstA[tid + i*256] = srcA[tid + i*256];
        int idx = noff[pxB];   // tap 0
        const float* img = g_h + ((size_t)(b*CH + half*32))*HW;
        unsigned char* bhi = nb + 8192;
#pragma unroll
        for (int ip = 0; ip < 16; ip++) {
            float v0 = (idx >= 0) ? img[idx] : 0.f; img += HW;
            float v1 = (idx >= 0) ? img[idx] : 0.f; img += HW;
            hi_store(bhi, SW128((uint32_t)(pxB*128 + (half*32 + ip*2)*2)), v0, v1);
        }
    }
    __syncthreads();

    float acc[2][2][4];
#pragma unroll
    for (int mt = 0; mt < 2; mt++)
#pragma unroll
        for (int nt = 0; nt < 2; nt++)
#pragma unroll
            for (int q = 0; q < 4; q++) acc[mt][nt][q] = 0.f;

    for (int c = 0; c < 18; c++) {
        int p = c & 1;
        uint32_t tb = sb + SM_OMT + p*OM_BUF;
#pragma unroll
        for (int ks = 0; ks < 4; ks++) {
            int kb = ks*32 + lkh;
            uint32_t ah[2][4], al[2][4], bh[4];
#pragma unroll
            for (int mt = 0; mt < 2; mt++)
                ldmx4(ah[mt], tb + SW128((uint32_t)((mt*16 + lrow)*128 + kb)));
            ldmx4(bh, tb + 8192 + SW128((uint32_t)((pxw + lrow)*128 + kb)));
#pragma unroll
            for (int mt = 0; mt < 2; mt++)
#pragma unroll
                for (int nt = 0; nt < 2; nt++)
                    mma_bf16(acc[mt][nt], ah[mt], bh[nt], bh[nt+2]);
#pragma unroll
            for (int mt = 0; mt < 2; mt++)
                ldmx4(al[mt], tb + 4096 + SW128((uint32_t)((mt*16 + lrow)*128 + kb)));
#pragma unroll
            for (int mt = 0; mt < 2; mt++)
#pragma unroll
                for (int nt = 0; nt < 2; nt++)
                    mma_bf16(acc[mt][nt], al[mt], bh[nt], bh[nt+2]);
        }
        if (c < 17) {
            int cn = c + 1;
            unsigned char* nb = smem + SM_OMT + (1-p)*OM_BUF;
            float4* dstA = (float4*)nb;
            const float4* srcA = (const float4*)((const unsigned char*)g_omA + (size_t)cn*8192);
#pragma unroll
            for (int i = 0; i < 2; i++) dstA[tid + i*256] = srcA[tid + i*256];
            int tap = cn >> 1, ichalf = cn & 1;
            int idx = noff[tap*128 + pxB];
            const float* img = g_h + ((size_t)(b*CH + ichalf*64 + half*32))*HW;
            unsigned char* bhi = nb + 8192;
#pragma unroll
            for (int ip = 0; ip < 16; ip++) {
                float v0 = (idx >= 0) ? img[idx] : 0.f; img += HW;
                float v1 = (idx >= 0) ? img[idx] : 0.f; img += HW;
                hi_store(bhi, SW128((uint32_t)(pxB*128 + (half*32 + ip*2)*2)), v0, v1);
            }
        }
        __syncthreads();
    }

    int g  = lane >> 2;
    int cx = (lane & 3) * 2;
#pragma unroll
    for (int mt = 0; mt < 2; mt++) {
#pragma unroll
        for (int nt = 0; nt < 2; nt++) {
            int px = hw0 + pxw + nt*8 + cx;
#pragma unroll
            for (int h2 = 0; h2 < 2; h2++) {
                int oc = mt*16 + g + h2*8;
                float v0 = acc[mt][nt][h2*2], v1 = acc[mt][nt][h2*2 + 1];
                if (oc < 18) {
                    float bbv = pb[oc];
                    float* d = g_offb + (size_t)(b*18 + oc)*HW + px;
                    *(float2*)d = make_float2(v0 + bbv, v1 + bbv);
                } else if (oc < 27) {
                    float bbv = mb[oc - 18];
                    float* d = g_mb + (size_t)(b*9 + oc - 18)*HW + px;
                    *(float2*)d = make_float2(1.f/(1.f + expf(-(v0 + bbv))),
                                              1.f/(1.f + expf(-(v1 + bbv))));
                }
            }
        }
    }
}

// ---------------- K5: deform conv via mma.sync bf16x3 -----------------------
#define SM_SI    0
#define SM_SW    18432
#define SM_TILE  36864
#define SMEM_DG  (SM_TILE + 2*65536)

__device__ __forceinline__ float dsample(const float* img, int4 id, float4 w) {
    float v = 0.f;
    if (id.x >= 0) v += w.x * img[id.x];
    if (id.y >= 0) v += w.y * img[id.y];
    if (id.z >= 0) v += w.z * img[id.z];
    if (id.w >= 0) v += w.w * img[id.w];
    return v;
}

__global__ __launch_bounds__(256, 1) void k_dgemm_tc() {
    extern __shared__ __align__(1024) unsigned char smem[];
    uint32_t sb = smem_u32(smem);
    int tid  = threadIdx.x;
    int lane = tid & 31;
    int wid  = tid >> 5;
    int pxg0 = blockIdx.x * 128;
    int b   = pxg0 >> 12;
    int hw0 = pxg0 & 4095;

    int4*   si = (int4*)(smem + SM_SI);
    float4* sw = (float4*)(smem + SM_SW);

    for (int e = tid; e < 1152; e += 256) {
        int n = e >> 7, h = e & 127;
        int hw = hw0 + h;
        int r = hw >> 6, c = hw & 63;
        float ox = g_offb[(size_t)(b*18 + n)*HW + hw];
        float oy = g_offb[(size_t)(b*18 + 9 + n)*HW + hw];
        float px = (float)(r + 1) + (float)(n/3 - 1) + ox;
        float py = (float)(c + 1) + (float)(n%3 - 1) + oy;
        float fx = floorf(px), fy = floorf(py);
        float qx0 = fminf(fmaxf(fx,       0.f), 65.f);
        float qx1 = fminf(fmaxf(fx + 1.f, 0.f), 65.f);
        float qy0 = fminf(fmaxf(fy,       0.f), 65.f);
        float qy1 = fminf(fmaxf(fy + 1.f, 0.f), 65.f);
        float pxc = fminf(fmaxf(px, 0.f), 65.f);
        float pyc = fminf(fmaxf(py, 0.f), 65.f);
        float glt = (1.f + (qx0 - pxc)) * (1.f + (qy0 - pyc));
        float grb = (1.f - (qx1 - pxc)) * (1.f - (qy1 - pyc));
        float glb = (1.f + (qx0 - pxc)) * (1.f - (qy1 - pyc));
        float grt = (1.f - (qx1 - pxc)) * (1.f + (qy0 - pyc));
        float mod = g_mb[(size_t)(b*9 + n)*HW + hw];
        int ix0 = (int)qx0, ix1 = (int)qx1, iy0 = (int)qy0, iy1 = (int)qy1;
#define ENC(qx,qy) (((qx)>=1 && (qx)<=64 && (qy)>=1 && (qy)<=64) ? (((qx)-1)*64 + ((qy)-1)) : -1)
        si[e] = make_int4(ENC(ix0,iy0), ENC(ix1,iy1), ENC(ix0,iy1), ENC(ix1,iy0));
#undef ENC
        sw[e] = make_float4(glt*mod, grb*mod, glb*mod, grt*mod);
    }
    __syncthreads();

    int pxB  = tid & 127;
    int half = tid >> 7;
    int ocb  = (wid >> 2) * 64;
    int pxb  = (wid & 3) * 32;
    int lrow = lane & 15;
    int lkh  = (lane >> 4) * 16;

    {
        float4* dstA = (float4*)(smem + SM_TILE);
        const float4* srcA = (const float4*)((const unsigned char*)g_wA);
#pragma unroll
        for (int i = 0; i < 8; i++) dstA[tid + i*256] = srcA[tid + i*256];
        int4   id = si[pxB];
        float4 wc = sw[pxB];
        const float* img = g_h + ((size_t)(b*CH + half*32))*HW;
        unsigned char* bhi = smem + SM_TILE + 32768;
        unsigned char* blo = bhi + 16384;
#pragma unroll
        for (int ip = 0; ip < 16; ip++) {
            float v0 = dsample(img, id, wc); img += HW;
            float v1 = dsample(img, id, wc); img += HW;
            split_store(bhi, blo, SW128((uint32_t)(pxB*128 + (half*32 + ip*2)*2)), v0, v1);
        }
    }
    __syncthreads();

    float acc[4][4][4];
#pragma unroll
    for (int mt = 0; mt < 4; mt++)
#pragma unroll
        for (int nt = 0; nt < 4; nt++)
#pragma unroll
            for (int q = 0; q < 4; q++) acc[mt][nt][q] = 0.f;

    for (int c = 0; c < 18; c++) {
        int p = c & 1;
        uint32_t tb = sb + SM_TILE + p*65536;
#pragma unroll
        for (int ks = 0; ks < 4; ks++) {
            int kb = ks*32 + lkh;
            uint32_t ah[4][4], al[4][4], bb[2][4];
#pragma unroll
            for (int mt = 0; mt < 4; mt++)
                ldmx4(ah[mt], tb + SW128((uint32_t)((ocb + mt*16 + lrow)*128 + kb)));
#pragma unroll
            for (int ntp = 0; ntp < 2; ntp++)
                ldmx4(bb[ntp], tb + 32768 + SW128((uint32_t)((pxb + ntp*16 + lrow)*128 + kb)));
#pragma unroll
            for (int mt = 0; mt < 4; mt++)
#pragma unroll
                for (int nt = 0; nt < 4; nt++)
                    mma_bf16(acc[mt][nt], ah[mt], bb[nt>>1][nt&1], bb[nt>>1][(nt&1)+2]);
#pragma unroll
            for (int mt = 0; mt < 4; mt++)
                ldmx4(al[mt], tb + 16384 + SW128((uint32_t)((ocb + mt*16 + lrow)*128 + kb)));
#pragma unroll
            for (int mt = 0; mt < 4; mt++)
#pragma unroll
                for (int nt = 0; nt < 4; nt++)
                    mma_bf16(acc[mt][nt], al[mt], bb[nt>>1][nt&1], bb[nt>>1][(nt&1)+2]);
#pragma unroll
            for (int ntp = 0; ntp < 2; ntp++)
                ldmx4(bb[ntp], tb + 49152 + SW128((uint32_t)((pxb + ntp*16 + lrow)*128 + kb)));
#pragma unroll
            for (int mt = 0; mt < 4; mt++)
#pragma unroll
                for (int nt = 0; nt < 4; nt++)
                    mma_bf16(acc[mt][nt], ah[mt], bb[nt>>1][nt&1], bb[nt>>1][(nt&1)+2]);
        }
        if (c < 17) {
            int cn = c + 1;
            unsigned char* nb = smem + SM_TILE + (1-p)*65536;
            float4* dstA = (float4*)nb;
            const float4* srcA = (const float4*)((const unsigned char*)g_wA + (size_t)cn*32768);
#pragma unroll
            for (int i = 0; i < 8; i++) dstA[tid + i*256] = srcA[tid + i*256];
            int tap = cn >> 1, ichalf = cn & 1;
            int m = tap*128 + pxB;
            int4   id = si[m];
            float4 wc = sw[m];
            const float* img = g_h + ((size_t)(b*CH + ichalf*64 + half*32))*HW;
            unsigned char* bhi = nb + 32768;
            unsigned char* blo = bhi + 16384;
#pragma unroll
            for (int ip = 0; ip < 16; ip++) {
                float v0 = dsample(img, id, wc); img += HW;
                float v1 = dsample(img, id, wc); img += HW;
                split_store(bhi, blo, SW128((uint32_t)(pxB*128 + (half*32 + ip*2)*2)), v0, v1);
            }
        }
        __syncthreads();
    }

    int g  = lane >> 2;
    int cx = (lane & 3) * 2;
#pragma unroll
    for (int mt = 0; mt < 4; mt++) {
#pragma unroll
        for (int nt = 0; nt < 4; nt++) {
            int oc = ocb + mt*16 + g;
            int px = pxb + nt*8 + cx;
            float* d0 = g_d + ((size_t)(b*CH + oc))*HW + hw0 + px;
            float* d1 = g_d + ((size_t)(b*CH + oc + 8))*HW + hw0 + px;
            *(float2*)d0 = make_float2(acc[mt][nt][0], acc[mt][nt][1]);
            *(float2*)d1 = make_float2(acc[mt][nt][2], acc[mt][nt][3]);
        }
    }
}

// ---------------- stats: per-channel mean / rstd (float4 loads) -------------
__global__ __launch_bounds__(256) void k_stats(const float* __restrict__ src,
                                               float* __restrict__ dst) {
    __shared__ float ss[256], sq[256];
    int ch = blockIdx.x, tid = threadIdx.x;
    float s = 0.f, s2 = 0.f;
    for (int i = tid; i < 8192; i += 256) {
        int b = i >> 10, h4 = i & 1023;
        float4 v = *(const float4*)&src[(size_t)(b*CH + ch)*HW + h4*4];
        s  += v.x + v.y + v.z + v.w;
        s2 += v.x*v.x + v.y*v.y + v.z*v.z + v.w*v.w;
    }
    ss[tid] = s; sq[tid] = s2;
    __syncthreads();
    for (int o = 128; o > 0; o >>= 1) {
        if (tid < o) { ss[tid] += ss[tid+o]; sq[tid] += sq[tid+o]; }
        __syncthreads();
    }
    if (tid == 0) {
        float mean = ss[0] * (1.f/32768.f);
        float var  = sq[0] * (1.f/32768.f) - mean*mean;
        dst[ch]      = mean;
        dst[CH + ch] = rsqrtf(var + 1e-5f);
    }
}

// ---------------- K7: fused bn1 + gelu + depthwise2 (halo tile) -------------
__global__ __launch_bounds__(256) void k_bngelu_dw2(const float* __restrict__ g,
                                                    const float* __restrict__ bv,
                                                    const float* __restrict__ w,
                                                    const float* __restrict__ bias) {
    __shared__ float T[66*68];
    int tid = threadIdx.x;
    int blk = blockIdx.x;          // (b, ch): 8*128
    int ch = blk & 127;
    float scale = g_s1[CH + ch] * g[ch];
    float shift = bv[ch] - g_s1[ch] * scale;
    const float* src = g_d + (size_t)blk*HW;

    for (int e = tid; e < 66*66; e += 256) {
        int r = e/66, c = e - (e/66)*66;
        int rr = r - 1, cc = c - 1;
        float v = 0.f;
        if ((unsigned)rr < 64u && (unsigned)cc < 64u) {
            float xn = src[rr*64 + cc] * scale + shift;
            v = 0.5f * xn * (1.f + erff(xn * 0.70710678118654752f));
        }
        T[r*68 + c] = v;
    }
    __syncthreads();

    const float* wc = w + ch*9;
    float w0 = wc[0], w1 = wc[1], w2 = wc[2], w3 = wc[3], w4 = wc[4],
          w5 = wc[5], w6 = wc[6], w7 = wc[7], w8 = wc[8];
    float bb = bias[ch];
    float* dst = g_u + (size_t)blk*HW;
#pragma unroll
    for (int i = 0; i < 16; i++) {
        int px = i*256 + tid;
        int r = px >> 6, c = px & 63;
        const float* t0 = T + r*68 + c;
        dst[px] = bb
            + w0*t0[0]     + w1*t0[1]     + w2*t0[2]
            + w3*t0[68]    + w4*t0[69]    + w5*t0[70]
            + w6*t0[136]   + w7*t0[137]   + w8*t0[138];
    }
}

// ---------------- K9: bn2 + relu -> out (float4) -----------------------------
__global__ __launch_bounds__(256) void k_bn2relu(const float* __restrict__ g,
                                                 const float* __restrict__ bv,
                                                 float* __restrict__ out) {
    int i = blockIdx.x * 256 + threadIdx.x;
    if (i >= BB*CH*HW/4) return;
    int ch = ((i << 2) >> 12) & (CH-1);
    float scale = g_s2[CH + ch] * g[ch];
    float shift = bv[ch] - g_s2[ch] * scale;
    float4 v = *(const float4*)&g_u[(size_t)i*4];
    float4 o;
    o.x = fmaxf(v.x*scale + shift, 0.f);
    o.y = fmaxf(v.y*scale + shift, 0.f);
    o.z = fmaxf(v.z*scale + shift, 0.f);
    o.w = fmaxf(v.w*scale + shift, 0.f);
    *(float4*)&out[(size_t)i*4] = o;
}

// ---------------- launch ----------------------------------------------------
extern "C" void kernel_launch(void* const* d_in, const int* in_sizes, int n_in,
                              void* d_out, int out_size) {
    const float* x1      = (const float*)d_in[0];
    const float* x2      = (const float*)d_in[1];
    const float* dw1_w   = (const float*)d_in[2];
    const float* dw1_b   = (const float*)d_in[3];
    const float* pw_w    = (const float*)d_in[4];
    const float* pw_b    = (const float*)d_in[5];
    const float* p_w     = (const float*)d_in[6];
    const float* p_b     = (const float*)d_in[7];
    const float* m_w     = (const float*)d_in[8];
    const float* m_b     = (const float*)d_in[9];
    const float* dcn_w   = (const float*)d_in[10];
    const float* bn1_g   = (const float*)d_in[11];
    const float* bn1_b   = (const float*)d_in[12];
    const float* dw2_w   = (const float*)d_in[13];
    const float* dw2_b   = (const float*)d_in[14];
    const float* bn2_g   = (const float*)d_in[15];
    const float* bn2_b   = (const float*)d_in[16];
    float* out = (float*)d_out;

    float *s1p, *s2p, *dp, *up;
    cudaGetSymbolAddress((void**)&s1p, g_s1);
    cudaGetSymbolAddress((void**)&s2p, g_s2);
    cudaGetSymbolAddress((void**)&dp,  g_d);
    cudaGetSymbolAddress((void**)&up,  g_u);

    cudaFuncSetAttribute(k_dgemm_tc,   cudaFuncAttributeMaxDynamicSharedMemorySize, SMEM_DG);
    cudaFuncSetAttribute(k_pw_tc,      cudaFuncAttributeMaxDynamicSharedMemorySize, SMEM_PW);
    cudaFuncSetAttribute(k_offmask_tc, cudaFuncAttributeMaxDynamicSharedMemorySize, SMEM_OM);

    int prep_items = 18*16384 + 4*16384 + 18*4096;
    k_prep <<<(prep_items + 255)/256, 256>>>(dcn_w, pw_w, p_w, m_w);
    k_updw1<<<BB*CC, 256>>>(x1, x2, dw1_w, dw1_b);
    k_pw_tc<<<PP/128, 256, SMEM_PW>>>(pw_b);
    k_offmask_tc<<<PP/128, 256, SMEM_OM>>>(p_b, m_b);
    k_dgemm_tc<<<PP/128, 256, SMEM_DG>>>();
    k_stats<<<CH, 256>>>(dp, s1p);
    k_bngelu_dw2<<<BB*CH, 256>>>(bn1_g, bn1_b, dw2_w, dw2_b);
    k_stats<<<CH, 256>>>(up, s2p);
    k_bn2relu<<<(BB*CH*HW/4 + 255)/256, 256>>>(bn2_g, bn2_b, out);
}